// round 13
// baseline (speedup 1.0000x reference)
#include <cuda_runtime.h>
#include <cuda_bf16.h>
#include <cstdint>

#define EMB  1024
#define NH   16
#define HD   64
#define SEQ  2048
#define NB   4
#define MTOT (NB * SEQ)   // 8192

// ---------------- scratch (__device__ globals; no allocs allowed) ----------
__device__ __nv_bfloat16 g_xh[(size_t)MTOT * EMB], g_xl[(size_t)MTOT * EMB];
__device__ __nv_bfloat16 g_ah[(size_t)MTOT * EMB], g_al[(size_t)MTOT * EMB];
__device__ __nv_bfloat16 g_wh[4][(size_t)EMB * EMB], g_wl[4][(size_t)EMB * EMB];
__device__ __nv_bfloat16 g_qh[(size_t)NB * NH * SEQ * HD], g_ql[(size_t)NB * NH * SEQ * HD];
__device__ __nv_bfloat16 g_kh[(size_t)NB * NH * SEQ * HD], g_kl[(size_t)NB * NH * SEQ * HD];
__device__ __nv_bfloat16 g_vh[(size_t)NB * NH * SEQ * HD], g_vl[(size_t)NB * NH * SEQ * HD];

// ---------------- helpers ---------------------------------------------------
__device__ __forceinline__ uint32_t smem_u32(const void* p) {
    uint32_t a;
    asm("{ .reg .u64 t; cvta.to.shared.u64 t, %1; cvt.u32.u64 %0, t; }"
        : "=r"(a) : "l"(p));
    return a;
}
__device__ __forceinline__ void ldsm4(uint32_t* r, uint32_t addr) {
    asm volatile("ldmatrix.sync.aligned.m8n8.x4.shared.b16 {%0,%1,%2,%3}, [%4];"
                 : "=r"(r[0]), "=r"(r[1]), "=r"(r[2]), "=r"(r[3]) : "r"(addr));
}
__device__ __forceinline__ void ldsm4t(uint32_t* r, uint32_t addr) {
    asm volatile("ldmatrix.sync.aligned.m8n8.x4.trans.shared.b16 {%0,%1,%2,%3}, [%4];"
                 : "=r"(r[0]), "=r"(r[1]), "=r"(r[2]), "=r"(r[3]) : "r"(addr));
}
__device__ __forceinline__ void mma16816(float* c, const uint32_t* a,
                                         uint32_t b0, uint32_t b1) {
    asm volatile(
        "mma.sync.aligned.m16n8k16.row.col.f32.bf16.bf16.f32 "
        "{%0,%1,%2,%3}, {%4,%5,%6,%7}, {%8,%9}, {%0,%1,%2,%3};"
        : "+f"(c[0]), "+f"(c[1]), "+f"(c[2]), "+f"(c[3])
        : "r"(a[0]), "r"(a[1]), "r"(a[2]), "r"(a[3]), "r"(b0), "r"(b1));
}
__device__ __forceinline__ uint32_t pack_bf16(float lo, float hi) {
    uint32_t r;
    asm("cvt.rn.bf16x2.f32 %0, %1, %2;" : "=r"(r) : "f"(hi), "f"(lo));
    return r;
}
__device__ __forceinline__ float bf16_round(float x) {
    return __bfloat162float(__float2bfloat16(x));
}
__device__ __forceinline__ void cp16cg(uint32_t saddr, const void* g) {
    asm volatile("cp.async.cg.shared.global [%0], [%1], 16;"
                 :: "r"(saddr), "l"(g) : "memory");
}
__device__ __forceinline__ void cp16ca(uint32_t saddr, const void* g) {
    asm volatile("cp.async.ca.shared.global [%0], [%1], 16;"
                 :: "r"(saddr), "l"(g) : "memory");
}
__device__ __forceinline__ void cp_commit() {
    asm volatile("cp.async.commit_group;" ::: "memory");
}
template <int N>
__device__ __forceinline__ void cp_wait() {
    asm volatile("cp.async.wait_group %0;" :: "n"(N) : "memory");
}

// ---------------- fused hi/lo split prepass (x + 4 weights) ------------------
__global__ void __launch_bounds__(256)
split_all_kernel(const float* __restrict__ x,
                 const float* __restrict__ wq, const float* __restrict__ wk,
                 const float* __restrict__ wv, const float* __restrict__ wo)
{
    const long long i4 = ((long long)blockIdx.x * 256 + threadIdx.x) * 4;
    const float* src;
    __nv_bfloat16 *hp, *lp;
    long long off;
    if (i4 < (long long)MTOT * EMB) {
        src = x; hp = g_xh; lp = g_xl; off = i4;
    } else {
        const long long r = i4 - (long long)MTOT * EMB;
        const int w = (int)(r >> 20);                  // EMB*EMB == 2^20
        off = r & ((1ll << 20) - 1);
        src = (w == 0) ? wq : (w == 1) ? wk : (w == 2) ? wv : wo;
        hp = g_wh[w]; lp = g_wl[w];
    }
    float4 v = *(const float4*)(src + off);
    float h0 = bf16_round(v.x), h1 = bf16_round(v.y);
    float h2 = bf16_round(v.z), h3 = bf16_round(v.w);
    *(uint32_t*)(hp + off)     = pack_bf16(h0, h1);
    *(uint32_t*)(hp + off + 2) = pack_bf16(h2, h3);
    *(uint32_t*)(lp + off)     = pack_bf16(v.x - h0, v.y - h1);
    *(uint32_t*)(lp + off + 2) = pack_bf16(v.z - h2, v.w - h3);
}

// ---------------- HMMA split-bf16 GEMM, 64x64 warp tiles ---------------------
// C[m,n] = sum_k A[m,k]*B[n,k].  128x128 CTA tile, 4 warps of 64x64, BK=32.
// Larger warp tile cuts LDSM bytes per MMA 1.5x (smem-crossbar-bound fix).
#define TS 40
#define TILE_B (128 * TS * 2)          // 10240 B per tile
#define STAGE_B (4 * TILE_B)           // 40960 B per stage (Ah, Al, Bh, Bl)
#define GEMM_SMEM (2 * STAGE_B)        // 81920 B -> 2 CTAs/SM

template <int MODE>
__device__ void hmma_gemm(const __nv_bfloat16* __restrict__ Ah_,
                          const __nv_bfloat16* __restrict__ Al_,
                          const __nv_bfloat16* __restrict__ Bh_,
                          const __nv_bfloat16* __restrict__ Bl_,
                          float* __restrict__ Cf,
                          __nv_bfloat16* __restrict__ Ch,
                          __nv_bfloat16* __restrict__ Cl,
                          float oscale)
{
    extern __shared__ char gsm[];
    const uint32_t sb = smem_u32(gsm);

    const int tid   = threadIdx.x;      // 0..127
    const int lane  = tid & 31;
    const int wid   = tid >> 5;         // 0..3
    const int warpM = wid >> 1;         // 0..1
    const int warpN = wid & 1;          // 0..1
    const int m0 = blockIdx.x * 128;
    const int n0 = blockIdx.y * 128;

    // prefetch: thread owns row 'tid' of all 4 tiles (4 x 16B units per tile)
    const __nv_bfloat16* pA0 = Ah_ + (size_t)(m0 + tid) * EMB;
    const __nv_bfloat16* pA1 = Al_ + (size_t)(m0 + tid) * EMB;
    const __nv_bfloat16* pB0 = Bh_ + (size_t)(n0 + tid) * EMB;
    const __nv_bfloat16* pB1 = Bl_ + (size_t)(n0 + tid) * EMB;
    const uint32_t so = (uint32_t)(tid * TS) * 2;

    float acc[4][8][4];
#pragma unroll
    for (int mt = 0; mt < 4; mt++)
#pragma unroll
        for (int nt = 0; nt < 8; nt++)
#pragma unroll
            for (int e = 0; e < 4; e++) acc[mt][nt][e] = 0.f;

    const int a_r = lane & 15;
    const int a_c = (lane >> 4) << 3;
    const int b_r = ((lane >> 4) << 3) + (lane & 7);
    const int b_c = ((lane >> 3) & 1) << 3;

    // prefetch chunk 0
    {
        const uint32_t stb = sb;
#pragma unroll
        for (int un = 0; un < 4; un++) {
            cp16ca(stb + so + un * 16,              pA0 + un * 8);
            cp16ca(stb + TILE_B + so + un * 16,     pA1 + un * 8);
            cp16ca(stb + 2 * TILE_B + so + un * 16, pB0 + un * 8);
            cp16ca(stb + 3 * TILE_B + so + un * 16, pB1 + un * 8);
        }
        cp_commit();
    }

    for (int ch = 0; ch < EMB / 32; ch++) {
        const int st = ch & 1;
        cp_wait<0>();
        __syncthreads();
        if (ch + 1 < EMB / 32) {
            const int k1 = (ch + 1) * 32;
            const uint32_t stb = sb + (st ^ 1) * STAGE_B;
#pragma unroll
            for (int un = 0; un < 4; un++) {
                cp16ca(stb + so + un * 16,              pA0 + k1 + un * 8);
                cp16ca(stb + TILE_B + so + un * 16,     pA1 + k1 + un * 8);
                cp16ca(stb + 2 * TILE_B + so + un * 16, pB0 + k1 + un * 8);
                cp16ca(stb + 3 * TILE_B + so + un * 16, pB1 + k1 + un * 8);
            }
            cp_commit();
        }

        const uint32_t stb = sb + st * STAGE_B;
        const uint32_t bAh = stb;
        const uint32_t bAl = stb + TILE_B;
        const uint32_t bBh = stb + 2 * TILE_B;
        const uint32_t bBl = stb + 3 * TILE_B;

#pragma unroll
        for (int ks = 0; ks < 2; ks++) {
            const int kb = ks << 4;
            uint32_t ah[4][4], al[4][4];
#pragma unroll
            for (int mt = 0; mt < 4; mt++) {
                const uint32_t off =
                    (uint32_t)((warpM * 64 + mt * 16 + a_r) * TS + kb + a_c) * 2;
                ldsm4(ah[mt], bAh + off);
                ldsm4(al[mt], bAl + off);
            }
#pragma unroll
            for (int ng = 0; ng < 4; ng++) {
                const uint32_t off =
                    (uint32_t)((warpN * 64 + ng * 16 + b_r) * TS + kb + b_c) * 2;
                uint32_t bh[4], bl[4];
                ldsm4(bh, bBh + off);
                ldsm4(bl, bBl + off);
                // pass-major: same accumulator reuse distance 8
#pragma unroll
                for (int mt = 0; mt < 4; mt++) {        // pass hh
                    mma16816(acc[mt][2 * ng],     ah[mt], bh[0], bh[1]);
                    mma16816(acc[mt][2 * ng + 1], ah[mt], bh[2], bh[3]);
                }
#pragma unroll
                for (int mt = 0; mt < 4; mt++) {        // pass hl
                    mma16816(acc[mt][2 * ng],     ah[mt], bl[0], bl[1]);
                    mma16816(acc[mt][2 * ng + 1], ah[mt], bl[2], bl[3]);
                }
#pragma unroll
                for (int mt = 0; mt < 4; mt++) {        // pass lh
                    mma16816(acc[mt][2 * ng],     al[mt], bh[0], bh[1]);
                    mma16816(acc[mt][2 * ng + 1], al[mt], bh[2], bh[3]);
                }
            }
        }
    }

#pragma unroll
    for (int mt = 0; mt < 4; mt++) {
#pragma unroll
        for (int nt = 0; nt < 8; nt++) {
            const int row = m0 + warpM * 64 + mt * 16 + (lane >> 2);
            const int col = n0 + warpN * 64 + nt * 8 + ((lane & 3) << 1);
#pragma unroll
            for (int half = 0; half < 2; half++) {
                const int r = row + half * 8;
                float vx = acc[mt][nt][2 * half]     * oscale;
                float vy = acc[mt][nt][2 * half + 1] * oscale;
                if (MODE == 0) {
                    *(float2*)&Cf[(size_t)r * EMB + col] = make_float2(vx, vy);
                } else {
                    const int b = r >> 11, s = r & (SEQ - 1);
                    const int h = col >> 6, d = col & (HD - 1);
                    const size_t o = ((((size_t)b * NH + h) * SEQ + s) << 6) + d;
                    float hx = bf16_round(vx), hy = bf16_round(vy);
                    *(uint32_t*)(Ch + o) = pack_bf16(hx, hy);
                    *(uint32_t*)(Cl + o) = pack_bf16(vx - hx, vy - hy);
                }
            }
        }
    }
}

__global__ void __launch_bounds__(128, 2) qkv_mma_kernel()
{
    const int z = blockIdx.z;
    if (z == 0)
        hmma_gemm<1>(g_xh, g_xl, g_wh[0], g_wl[0], nullptr, g_qh, g_ql, 0.125f);
    else if (z == 1)
        hmma_gemm<1>(g_xh, g_xl, g_wh[1], g_wl[1], nullptr, g_kh, g_kl, 1.0f);
    else
        hmma_gemm<1>(g_xh, g_xl, g_wh[2], g_wl[2], nullptr, g_vh, g_vl, 1.0f);
}
__global__ void __launch_bounds__(128, 2) oproj_mma_kernel(float* __restrict__ out)
{
    hmma_gemm<0>(g_ah, g_al, g_wh[3], g_wl[3], out, nullptr, nullptr, 1.0f);
}

// ---------------- HMMA flash attention v4 (unchanged from R12) ---------------
#define ATB 16384
#define ASMEM (6 * ATB + SEQ * 4)    // 106496 B -> 2 CTAs/SM

__device__ __forceinline__ uint32_t swz(int r, int u) {
    return (uint32_t)(r * 128 + (((u ^ r) & 7) << 4) + (u & ~7) * 16);
}

__global__ void __launch_bounds__(256, 2)
attn_hmma_kernel(const int* __restrict__ mask)
{
    extern __shared__ char sm[];
    const uint32_t T0 = smem_u32(sm);
    const uint32_t T2 = T0 + 2 * ATB;
    const uint32_t T4 = T0 + 4 * ATB;
    int* sMask = (int*)(sm + 6 * ATB);

    const int tid  = threadIdx.x;
    const int lane = tid & 31;
    const int wid  = tid >> 5;
    const int qt   = blockIdx.x;
    const int h    = blockIdx.y;
    const int b    = blockIdx.z;

    const size_t hb = ((size_t)b * NH + h) * SEQ * HD;
    const int* mrow = mask + b * SEQ;

    for (int u = tid; u < 1024; u += 256) {
        const int r = u >> 3, c = u & 7;
        const uint32_t sw = swz(r, c);
        const size_t gq = hb + (size_t)(qt * 128 + r) * HD + c * 8;
        const size_t gk = hb + (size_t)r * HD + c * 8;
        cp16cg(T4 + sw, g_qh + gq);
        cp16cg(T4 + ATB + sw, g_ql + gq);
        cp16cg(T0 + sw, g_kh + gk);
        cp16cg(T0 + ATB + sw, g_kl + gk);
    }
    for (int i = tid; i < SEQ; i += 256) sMask[i] = mrow[i];
    cp_commit();
    cp_wait<0>();
    __syncthreads();

    const int a_r = lane & 15;
    const int a_u = lane >> 4;
    const int b_r = ((lane >> 4) << 3) + (lane & 7);
    const int b_u = (lane >> 3) & 1;
    const int v_kr = ((lane >> 3) & 1) * 8 + (lane & 7);
    const int v_u  = lane >> 4;

    const int tq   = lane & 3;
    const int row0 = qt * 128 + wid * 16 + (lane >> 2);
    const int row1 = row0 + 8;
    const int qrow = wid * 16 + a_r;

    uint32_t qfh[4][4], qfl[4][4];
#pragma unroll
    for (int kc = 0; kc < 4; kc++) {
        const uint32_t qoff = swz(qrow, kc * 2 + a_u);
        ldsm4(qfh[kc], T4 + qoff);
        ldsm4(qfl[kc], T4 + ATB + qoff);
    }
    __syncthreads();

    float m0 = -1e30f, m1 = -1e30f, l0 = 0.f, l1 = 0.f;
    float accO[8][4];
#pragma unroll
    for (int nt = 0; nt < 8; nt++)
#pragma unroll
        for (int e = 0; e < 4; e++) accO[nt][e] = 0.f;

    for (int kt = 0; kt <= qt; kt++) {
        if (kt > 0) {
            cp_wait<0>();
            __syncthreads();
        }

        for (int u = tid; u < 1024; u += 256) {
            const int r = u >> 3, c = u & 7;
            const uint32_t sw = swz(r, c);
            const size_t gv = hb + (size_t)(kt * 128 + r) * HD + c * 8;
            cp16cg(T2 + sw, g_vh + gv);
            cp16cg(T2 + ATB + sw, g_vl + gv);
        }
        cp_commit();
        if (kt < qt) {
            const uint32_t Kn = ((kt + 1) & 1) ? T4 : T0;
            for (int u = tid; u < 1024; u += 256) {
                const int r = u >> 3, c = u & 7;
                const uint32_t sw = swz(r, c);
                const size_t gk = hb + (size_t)((kt + 1) * 128 + r) * HD + c * 8;
                cp16cg(Kn + sw, g_kh + gk);
                cp16cg(Kn + ATB + sw, g_kl + gk);
            }
            cp_commit();
        }

        const uint32_t bKh = (kt & 1) ? T4 : T0;
        const uint32_t bKl = bKh + ATB;

#pragma unroll
        for (int nh = 0; nh < 2; nh++) {
            float sacc[8][4];
#pragma unroll
            for (int nt = 0; nt < 8; nt++)
#pragma unroll
                for (int e = 0; e < 4; e++) sacc[nt][e] = 0.f;

#pragma unroll
            for (int kc = 0; kc < 4; kc++) {
#pragma unroll
                for (int np = 0; np < 2; np++) {
                    uint32_t kh4[2][4], kl4[2][4];
#pragma unroll
                    for (int j = 0; j < 2; j++) {
                        const int krow = (nh * 4 + np * 2 + j) * 16 + b_r;
                        const uint32_t koff = swz(krow, kc * 2 + b_u);
                        ldsm4(kh4[j], bKh + koff);
                        ldsm4(kl4[j], bKl + koff);
                    }
#pragma unroll
                    for (int j = 0; j < 2; j++) {
                        const int n2 = np * 2 + j;
                        mma16816(sacc[2 * n2],     qfh[kc], kh4[j][0], kh4[j][1]);
                        mma16816(sacc[2 * n2 + 1], qfh[kc], kh4[j][2], kh4[j][3]);
                    }
#pragma unroll
                    for (int j = 0; j < 2; j++) {
                        const int n2 = np * 2 + j;
                        mma16816(sacc[2 * n2],     qfh[kc], kl4[j][0], kl4[j][1]);
                        mma16816(sacc[2 * n2 + 1], qfh[kc], kl4[j][2], kl4[j][3]);
                    }
#pragma unroll
                    for (int j = 0; j < 2; j++) {
                        const int n2 = np * 2 + j;
                        mma16816(sacc[2 * n2],     qfl[kc], kh4[j][0], kh4[j][1]);
                        mma16816(sacc[2 * n2 + 1], qfl[kc], kh4[j][2], kh4[j][3]);
                    }
                }
            }

#pragma unroll
            for (int nt = 0; nt < 8; nt++) {
                const int c0 = nh * 64 + nt * 8 + tq * 2;
                const int k0 = kt * 128 + c0;
                const bool v0 = sMask[k0] != 0;
                const bool v1 = sMask[k0 + 1] != 0;
                if (!(v0 && k0     <= row0)) sacc[nt][0] = -1e30f;
                if (!(v1 && k0 + 1 <= row0)) sacc[nt][1] = -1e30f;
                if (!(v0 && k0     <= row1)) sacc[nt][2] = -1e30f;
                if (!(v1 && k0 + 1 <= row1)) sacc[nt][3] = -1e30f;
            }

            float r0 = -1e30f, r1 = -1e30f;
#pragma unroll
            for (int nt = 0; nt < 8; nt++) {
                r0 = fmaxf(r0, fmaxf(sacc[nt][0], sacc[nt][1]));
                r1 = fmaxf(r1, fmaxf(sacc[nt][2], sacc[nt][3]));
            }
            r0 = fmaxf(r0, __shfl_xor_sync(0xffffffffu, r0, 1));
            r0 = fmaxf(r0, __shfl_xor_sync(0xffffffffu, r0, 2));
            r1 = fmaxf(r1, __shfl_xor_sync(0xffffffffu, r1, 1));
            r1 = fmaxf(r1, __shfl_xor_sync(0xffffffffu, r1, 2));

            const float mn0 = fmaxf(m0, r0), mn1 = fmaxf(m1, r1);
            const float al0 = __expf(m0 - mn0), al1 = __expf(m1 - mn1);
            m0 = mn0; m1 = mn1;

            float s0 = 0.f, s1 = 0.f;
#pragma unroll
            for (int nt = 0; nt < 8; nt++) {
                sacc[nt][0] = __expf(sacc[nt][0] - mn0); s0 += sacc[nt][0];
                sacc[nt][1] = __expf(sacc[nt][1] - mn0); s0 += sacc[nt][1];
                sacc[nt][2] = __expf(sacc[nt][2] - mn1); s1 += sacc[nt][2];
                sacc[nt][3] = __expf(sacc[nt][3] - mn1); s1 += sacc[nt][3];
            }
            s0 += __shfl_xor_sync(0xffffffffu, s0, 1);
            s0 += __shfl_xor_sync(0xffffffffu, s0, 2);
            s1 += __shfl_xor_sync(0xffffffffu, s1, 1);
            s1 += __shfl_xor_sync(0xffffffffu, s1, 2);
            l0 = l0 * al0 + s0;
            l1 = l1 * al1 + s1;
#pragma unroll
            for (int nt = 0; nt < 8; nt++) {
                accO[nt][0] *= al0; accO[nt][1] *= al0;
                accO[nt][2] *= al1; accO[nt][3] *= al1;
            }

            if (nh == 0) {
                if (kt < qt) cp_wait<1>(); else cp_wait<0>();
                __syncthreads();
            }

#pragma unroll
            for (int c2l = 0; c2l < 4; c2l++) {
                const int c2 = nh * 4 + c2l;
                const float p00 = sacc[2 * c2l][0],     p01 = sacc[2 * c2l][1];
                const float p02 = sacc[2 * c2l][2],     p03 = sacc[2 * c2l][3];
                const float p10 = sacc[2 * c2l + 1][0], p11 = sacc[2 * c2l + 1][1];
                const float p12 = sacc[2 * c2l + 1][2], p13 = sacc[2 * c2l + 1][3];
                const float h00 = bf16_round(p00), h01 = bf16_round(p01);
                const float h02 = bf16_round(p02), h03 = bf16_round(p03);
                const float h10 = bf16_round(p10), h11 = bf16_round(p11);
                const float h12 = bf16_round(p12), h13 = bf16_round(p13);
                uint32_t ph[4], pl[4];
                ph[0] = pack_bf16(h00, h01); ph[1] = pack_bf16(h02, h03);
                ph[2] = pack_bf16(h10, h11); ph[3] = pack_bf16(h12, h13);
                pl[0] = pack_bf16(p00 - h00, p01 - h01);
                pl[1] = pack_bf16(p02 - h02, p03 - h03);
                pl[2] = pack_bf16(p10 - h10, p11 - h11);
                pl[3] = pack_bf16(p12 - h12, p13 - h13);

#pragma unroll
                for (int dq = 0; dq < 2; dq++) {
                    uint32_t vh4[2][4], vl4[2][4];
#pragma unroll
                    for (int j = 0; j < 2; j++) {
                        const int dp = dq * 2 + j;
                        const int vrow = c2 * 16 + v_kr;
                        const uint32_t voff = swz(vrow, dp * 2 + v_u);
                        ldsm4t(vh4[j], T2 + voff);
                        ldsm4t(vl4[j], T2 + ATB + voff);
                    }
#pragma unroll
                    for (int j = 0; j < 2; j++) {
                        const int dp = dq * 2 + j;
                        mma16816(accO[2 * dp],     ph, vh4[j][0], vh4[j][1]);
                        mma16816(accO[2 * dp + 1], ph, vh4[j][2], vh4[j][3]);
                    }
#pragma unroll
                    for (int j = 0; j < 2; j++) {
                        const int dp = dq * 2 + j;
                        mma16816(accO[2 * dp],     ph, vl4[j][0], vl4[j][1]);
                        mma16816(accO[2 * dp + 1], ph, vl4[j][2], vl4[j][3]);
                    }
#pragma unroll
                    for (int j = 0; j < 2; j++) {
                        const int dp = dq * 2 + j;
                        mma16816(accO[2 * dp],     pl, vh4[j][0], vh4[j][1]);
                        mma16816(accO[2 * dp + 1], pl, vh4[j][2], vh4[j][3]);
                    }
                }
            }
        }
    }

    const float i0 = 1.f / l0, i1 = 1.f / l1;
    const size_t ob0 = ((size_t)b * SEQ + row0) * EMB + h * HD;
    const size_t ob1 = ((size_t)b * SEQ + row1) * EMB + h * HD;
#pragma unroll
    for (int nt = 0; nt < 8; nt++) {
        const int col = nt * 8 + tq * 2;
        const float x0 = accO[nt][0] * i0, y0 = accO[nt][1] * i0;
        const float x1 = accO[nt][2] * i1, y1 = accO[nt][3] * i1;
        const float hx0 = bf16_round(x0), hy0 = bf16_round(y0);
        const float hx1 = bf16_round(x1), hy1 = bf16_round(y1);
        *(uint32_t*)(g_ah + ob0 + col) = pack_bf16(hx0, hy0);
        *(uint32_t*)(g_al + ob0 + col) = pack_bf16(x0 - hx0, y0 - hy0);
        *(uint32_t*)(g_ah + ob1 + col) = pack_bf16(hx1, hy1);
        *(uint32_t*)(g_al + ob1 + col) = pack_bf16(x1 - hx1, y1 - hy1);
    }
}

// ---------------------------------------------------------------------------
extern "C" void kernel_launch(void* const* d_in, const int* in_sizes, int n_in,
                              void* d_out, int out_size)
{
    const float* x    = (const float*)d_in[0];
    const int*   mask = (const int*)d_in[1];
    const float* wq   = (const float*)d_in[2];
    const float* wk   = (const float*)d_in[3];
    const float* wv   = (const float*)d_in[4];
    const float* wo   = (const float*)d_in[5];
    float* out = (float*)d_out;

    const int total4 = (MTOT * EMB + 4 * EMB * EMB) / 4;
    split_all_kernel<<<total4 / 256, 256>>>(x, wq, wk, wv, wo);

    cudaFuncSetAttribute(qkv_mma_kernel,
                         cudaFuncAttributeMaxDynamicSharedMemorySize, GEMM_SMEM);
    qkv_mma_kernel<<<dim3(MTOT / 128, EMB / 128, 3), 128, GEMM_SMEM>>>();

    cudaFuncSetAttribute(attn_hmma_kernel,
                         cudaFuncAttributeMaxDynamicSharedMemorySize, ASMEM);
    attn_hmma_kernel<<<dim3(SEQ / 128, NH, NB), 256, ASMEM>>>(mask);

    cudaFuncSetAttribute(oproj_mma_kernel,
                         cudaFuncAttributeMaxDynamicSharedMemorySize, GEMM_SMEM);
    oproj_mma_kernel<<<dim3(MTOT / 128, EMB / 128, 1), 128, GEMM_SMEM>>>(out);
}

// round 14
// speedup vs baseline: 1.7026x; 1.7026x over previous
#include <cuda_runtime.h>
#include <cuda_bf16.h>
#include <cuda_fp16.h>
#include <cstdint>

#define EMB  1024
#define NH   16
#define HD   64
#define SEQ  2048
#define NB   4
#define MTOT (NB * SEQ)   // 8192

// ---------------- scratch (__device__ globals; no allocs allowed) ----------
__device__ __half g_xh[(size_t)MTOT * EMB], g_xl[(size_t)MTOT * EMB];
__device__ __half g_ah[(size_t)MTOT * EMB], g_al[(size_t)MTOT * EMB];
__device__ __half g_wf[4][(size_t)EMB * EMB];
__device__ __nv_bfloat16 g_qh[(size_t)NB * NH * SEQ * HD], g_ql[(size_t)NB * NH * SEQ * HD];
__device__ __nv_bfloat16 g_kh[(size_t)NB * NH * SEQ * HD], g_kl[(size_t)NB * NH * SEQ * HD];
__device__ __nv_bfloat16 g_vh[(size_t)NB * NH * SEQ * HD], g_vl[(size_t)NB * NH * SEQ * HD];

// ---------------- helpers ---------------------------------------------------
__device__ __forceinline__ uint32_t smem_u32(const void* p) {
    uint32_t a;
    asm("{ .reg .u64 t; cvta.to.shared.u64 t, %1; cvt.u32.u64 %0, t; }"
        : "=r"(a) : "l"(p));
    return a;
}
__device__ __forceinline__ void ldsm4(uint32_t* r, uint32_t addr) {
    asm volatile("ldmatrix.sync.aligned.m8n8.x4.shared.b16 {%0,%1,%2,%3}, [%4];"
                 : "=r"(r[0]), "=r"(r[1]), "=r"(r[2]), "=r"(r[3]) : "r"(addr));
}
__device__ __forceinline__ void ldsm4t(uint32_t* r, uint32_t addr) {
    asm volatile("ldmatrix.sync.aligned.m8n8.x4.trans.shared.b16 {%0,%1,%2,%3}, [%4];"
                 : "=r"(r[0]), "=r"(r[1]), "=r"(r[2]), "=r"(r[3]) : "r"(addr));
}
// bf16 MMA (attention)
__device__ __forceinline__ void mma16816(float* c, const uint32_t* a,
                                         uint32_t b0, uint32_t b1) {
    asm volatile(
        "mma.sync.aligned.m16n8k16.row.col.f32.bf16.bf16.f32 "
        "{%0,%1,%2,%3}, {%4,%5,%6,%7}, {%8,%9}, {%0,%1,%2,%3};"
        : "+f"(c[0]), "+f"(c[1]), "+f"(c[2]), "+f"(c[3])
        : "r"(a[0]), "r"(a[1]), "r"(a[2]), "r"(a[3]), "r"(b0), "r"(b1));
}
// fp16 MMA (projection GEMMs)
__device__ __forceinline__ void mma16816h(float* c, const uint32_t* a,
                                          uint32_t b0, uint32_t b1) {
    asm volatile(
        "mma.sync.aligned.m16n8k16.row.col.f32.f16.f16.f32 "
        "{%0,%1,%2,%3}, {%4,%5,%6,%7}, {%8,%9}, {%0,%1,%2,%3};"
        : "+f"(c[0]), "+f"(c[1]), "+f"(c[2]), "+f"(c[3])
        : "r"(a[0]), "r"(a[1]), "r"(a[2]), "r"(a[3]), "r"(b0), "r"(b1));
}
__device__ __forceinline__ uint32_t pack_bf16(float lo, float hi) {
    uint32_t r;
    asm("cvt.rn.bf16x2.f32 %0, %1, %2;" : "=r"(r) : "f"(hi), "f"(lo));
    return r;
}
__device__ __forceinline__ uint32_t pack_f16(float lo, float hi) {
    uint32_t r;
    asm("cvt.rn.f16x2.f32 %0, %1, %2;" : "=r"(r) : "f"(hi), "f"(lo));
    return r;
}
__device__ __forceinline__ float bf16_round(float x) {
    return __bfloat162float(__float2bfloat16(x));
}
__device__ __forceinline__ float f16_round(float x) {
    return __half2float(__float2half_rn(x));
}
__device__ __forceinline__ void cp16cg(uint32_t saddr, const void* g) {
    asm volatile("cp.async.cg.shared.global [%0], [%1], 16;"
                 :: "r"(saddr), "l"(g) : "memory");
}
__device__ __forceinline__ void cp16ca(uint32_t saddr, const void* g) {
    asm volatile("cp.async.ca.shared.global [%0], [%1], 16;"
                 :: "r"(saddr), "l"(g) : "memory");
}
__device__ __forceinline__ void cp_commit() {
    asm volatile("cp.async.commit_group;" ::: "memory");
}
template <int N>
__device__ __forceinline__ void cp_wait() {
    asm volatile("cp.async.wait_group %0;" :: "n"(N) : "memory");
}

// ---------------- fused split prepass: x -> fp16 hi/lo, w -> fp16 ------------
__global__ void __launch_bounds__(256)
split_all_kernel(const float* __restrict__ x,
                 const float* __restrict__ wq, const float* __restrict__ wk,
                 const float* __restrict__ wv, const float* __restrict__ wo)
{
    const long long i4 = ((long long)blockIdx.x * 256 + threadIdx.x) * 4;
    if (i4 < (long long)MTOT * EMB) {
        float4 v = *(const float4*)(x + i4);
        float h0 = f16_round(v.x), h1 = f16_round(v.y);
        float h2 = f16_round(v.z), h3 = f16_round(v.w);
        *(uint32_t*)(g_xh + i4)     = pack_f16(h0, h1);
        *(uint32_t*)(g_xh + i4 + 2) = pack_f16(h2, h3);
        *(uint32_t*)(g_xl + i4)     = pack_f16(v.x - h0, v.y - h1);
        *(uint32_t*)(g_xl + i4 + 2) = pack_f16(v.z - h2, v.w - h3);
    } else {
        const long long r = i4 - (long long)MTOT * EMB;
        const int w = (int)(r >> 20);                  // EMB*EMB == 2^20
        const long long off = r & ((1ll << 20) - 1);
        const float* src = (w == 0) ? wq : (w == 1) ? wk : (w == 2) ? wv : wo;
        float4 v = *(const float4*)(src + off);
        *(uint32_t*)(g_wf[w] + off)     = pack_f16(f16_round(v.x), f16_round(v.y));
        *(uint32_t*)(g_wf[w] + off + 2) = pack_f16(f16_round(v.z), f16_round(v.w));
    }
}

// ---------------- fp16 2-MMA split GEMM, cp.async.ca pipeline, 2 CTA/SM ------
// C[m,n] = sum_k A[m,k]*B[n,k]; A split fp16 hi/lo, B single fp16.
// 128x128 CTA tile, 8 warps of 32x64, BK=32, pass-major emission.
#define TS 40
#define TILE_B (128 * TS * 2)          // 10240 B per tile
#define STAGE_B (3 * TILE_B)           // 30720 B per stage (Ah, Al, Bf)
#define GEMM_SMEM (2 * STAGE_B)        // 61440 B -> 2 CTAs/SM

template <int MODE>
__device__ void hmma_gemm(const __half* __restrict__ Ah_,
                          const __half* __restrict__ Al_,
                          const __half* __restrict__ Bf_,
                          float* __restrict__ Cf,
                          __nv_bfloat16* __restrict__ Ch,
                          __nv_bfloat16* __restrict__ Cl,
                          float oscale)
{
    extern __shared__ char gsm[];
    const uint32_t sb = smem_u32(gsm);

    const int tid   = threadIdx.x;
    const int lane  = tid & 31;
    const int wid   = tid >> 5;
    const int warpM = wid & 3;
    const int warpN = wid >> 2;
    const int m0 = blockIdx.x * 128;
    const int n0 = blockIdx.y * 128;

    const int pr0 = tid >> 1;
    const int pu0 = (tid & 1) << 1;
    const __half* pA0 = Ah_ + (size_t)(m0 + pr0) * EMB + pu0 * 8;
    const __half* pA1 = Al_ + (size_t)(m0 + pr0) * EMB + pu0 * 8;
    const __half* pB0 = Bf_ + (size_t)(n0 + pr0) * EMB + pu0 * 8;
    const uint32_t so = (uint32_t)(pr0 * TS + pu0 * 8) * 2;

    float acc[2][8][4];
#pragma unroll
    for (int mt = 0; mt < 2; mt++)
#pragma unroll
        for (int nt = 0; nt < 8; nt++)
#pragma unroll
            for (int e = 0; e < 4; e++) acc[mt][nt][e] = 0.f;

    const int a_r = lane & 15;
    const int a_c = (lane >> 4) << 3;
    const int b_r = ((lane >> 4) << 3) + (lane & 7);
    const int b_c = ((lane >> 3) & 1) << 3;

    {
        const uint32_t stb = sb;
        cp16ca(stb + so,                   pA0);
        cp16ca(stb + so + 16,              pA0 + 8);
        cp16ca(stb + TILE_B + so,          pA1);
        cp16ca(stb + TILE_B + so + 16,     pA1 + 8);
        cp16ca(stb + 2 * TILE_B + so,      pB0);
        cp16ca(stb + 2 * TILE_B + so + 16, pB0 + 8);
        cp_commit();
    }

    for (int ch = 0; ch < EMB / 32; ch++) {
        const int st = ch & 1;
        cp_wait<0>();
        __syncthreads();
        if (ch + 1 < EMB / 32) {
            const int k1 = (ch + 1) * 32;
            const uint32_t stb = sb + (st ^ 1) * STAGE_B;
            cp16ca(stb + so,                   pA0 + k1);
            cp16ca(stb + so + 16,              pA0 + k1 + 8);
            cp16ca(stb + TILE_B + so,          pA1 + k1);
            cp16ca(stb + TILE_B + so + 16,     pA1 + k1 + 8);
            cp16ca(stb + 2 * TILE_B + so,      pB0 + k1);
            cp16ca(stb + 2 * TILE_B + so + 16, pB0 + k1 + 8);
            cp_commit();
        }

        const uint32_t stb = sb + st * STAGE_B;
        const uint32_t bAh = stb;
        const uint32_t bAl = stb + TILE_B;
        const uint32_t bBf = stb + 2 * TILE_B;

#pragma unroll
        for (int ks = 0; ks < 2; ks++) {
            const int kb = ks << 4;
            uint32_t ah[2][4], al[2][4];
#pragma unroll
            for (int mt = 0; mt < 2; mt++) {
                const uint32_t off =
                    (uint32_t)((warpM * 32 + mt * 16 + a_r) * TS + kb + a_c) * 2;
                ldsm4(ah[mt], bAh + off);
                ldsm4(al[mt], bAl + off);
            }
#pragma unroll
            for (int ng = 0; ng < 4; ng++) {
                const uint32_t off =
                    (uint32_t)((warpN * 64 + ng * 16 + b_r) * TS + kb + b_c) * 2;
                uint32_t bf[4];
                ldsm4(bf, bBf + off);
                // pass-major: same accumulator reuse distance 4
#pragma unroll
                for (int mt = 0; mt < 2; mt++) {        // pass hi
                    mma16816h(acc[mt][2 * ng],     ah[mt], bf[0], bf[1]);
                    mma16816h(acc[mt][2 * ng + 1], ah[mt], bf[2], bf[3]);
                }
#pragma unroll
                for (int mt = 0; mt < 2; mt++) {        // pass lo
                    mma16816h(acc[mt][2 * ng],     al[mt], bf[0], bf[1]);
                    mma16816h(acc[mt][2 * ng + 1], al[mt], bf[2], bf[3]);
                }
            }
        }
    }

#pragma unroll
    for (int mt = 0; mt < 2; mt++) {
#pragma unroll
        for (int nt = 0; nt < 8; nt++) {
            const int row = m0 + warpM * 32 + mt * 16 + (lane >> 2);
            const int col = n0 + warpN * 64 + nt * 8 + ((lane & 3) << 1);
#pragma unroll
            for (int half = 0; half < 2; half++) {
                const int r = row + half * 8;
                float vx = acc[mt][nt][2 * half]     * oscale;
                float vy = acc[mt][nt][2 * half + 1] * oscale;
                if (MODE == 0) {
                    *(float2*)&Cf[(size_t)r * EMB + col] = make_float2(vx, vy);
                } else {
                    const int b = r >> 11, s = r & (SEQ - 1);
                    const int h = col >> 6, d = col & (HD - 1);
                    const size_t o = ((((size_t)b * NH + h) * SEQ + s) << 6) + d;
                    float hx = bf16_round(vx), hy = bf16_round(vy);
                    *(uint32_t*)(Ch + o) = pack_bf16(hx, hy);
                    *(uint32_t*)(Cl + o) = pack_bf16(vx - hx, vy - hy);
                }
            }
        }
    }
}

__global__ void __launch_bounds__(256, 2) qkv_mma_kernel()
{
    const int z = blockIdx.z;
    if (z == 0)
        hmma_gemm<1>(g_xh, g_xl, g_wf[0], nullptr, g_qh, g_ql, 0.125f);
    else if (z == 1)
        hmma_gemm<1>(g_xh, g_xl, g_wf[1], nullptr, g_kh, g_kl, 1.0f);
    else
        hmma_gemm<1>(g_xh, g_xl, g_wf[2], nullptr, g_vh, g_vl, 1.0f);
}
__global__ void __launch_bounds__(256, 2) oproj_mma_kernel(float* __restrict__ out)
{
    hmma_gemm<0>(g_ah, g_al, g_wf[3], out, nullptr, nullptr, 1.0f);
}

// ---------------- HMMA flash attention v4 (bf16 3-MMA, as in R12) ------------
#define ATB 16384
#define ASMEM (6 * ATB + SEQ * 4)    // 106496 B -> 2 CTAs/SM

__device__ __forceinline__ uint32_t swz(int r, int u) {
    return (uint32_t)(r * 128 + (((u ^ r) & 7) << 4) + (u & ~7) * 16);
}

__global__ void __launch_bounds__(256, 2)
attn_hmma_kernel(const int* __restrict__ mask)
{
    extern __shared__ char sm[];
    const uint32_t T0 = smem_u32(sm);
    const uint32_t T2 = T0 + 2 * ATB;
    const uint32_t T4 = T0 + 4 * ATB;
    int* sMask = (int*)(sm + 6 * ATB);

    const int tid  = threadIdx.x;
    const int lane = tid & 31;
    const int wid  = tid >> 5;
    const int qt   = blockIdx.x;
    const int h    = blockIdx.y;
    const int b    = blockIdx.z;

    const size_t hb = ((size_t)b * NH + h) * SEQ * HD;
    const int* mrow = mask + b * SEQ;

    for (int u = tid; u < 1024; u += 256) {
        const int r = u >> 3, c = u & 7;
        const uint32_t sw = swz(r, c);
        const size_t gq = hb + (size_t)(qt * 128 + r) * HD + c * 8;
        const size_t gk = hb + (size_t)r * HD + c * 8;
        cp16cg(T4 + sw, g_qh + gq);
        cp16cg(T4 + ATB + sw, g_ql + gq);
        cp16cg(T0 + sw, g_kh + gk);
        cp16cg(T0 + ATB + sw, g_kl + gk);
    }
    for (int i = tid; i < SEQ; i += 256) sMask[i] = mrow[i];
    cp_commit();
    cp_wait<0>();
    __syncthreads();

    const int a_r = lane & 15;
    const int a_u = lane >> 4;
    const int b_r = ((lane >> 4) << 3) + (lane & 7);
    const int b_u = (lane >> 3) & 1;
    const int v_kr = ((lane >> 3) & 1) * 8 + (lane & 7);
    const int v_u  = lane >> 4;

    const int tq   = lane & 3;
    const int row0 = qt * 128 + wid * 16 + (lane >> 2);
    const int row1 = row0 + 8;
    const int qrow = wid * 16 + a_r;

    uint32_t qfh[4][4], qfl[4][4];
#pragma unroll
    for (int kc = 0; kc < 4; kc++) {
        const uint32_t qoff = swz(qrow, kc * 2 + a_u);
        ldsm4(qfh[kc], T4 + qoff);
        ldsm4(qfl[kc], T4 + ATB + qoff);
    }
    __syncthreads();

    float m0 = -1e30f, m1 = -1e30f, l0 = 0.f, l1 = 0.f;
    float accO[8][4];
#pragma unroll
    for (int nt = 0; nt < 8; nt++)
#pragma unroll
        for (int e = 0; e < 4; e++) accO[nt][e] = 0.f;

    for (int kt = 0; kt <= qt; kt++) {
        if (kt > 0) {
            cp_wait<0>();
            __syncthreads();
        }

        for (int u = tid; u < 1024; u += 256) {
            const int r = u >> 3, c = u & 7;
            const uint32_t sw = swz(r, c);
            const size_t gv = hb + (size_t)(kt * 128 + r) * HD + c * 8;
            cp16cg(T2 + sw, g_vh + gv);
            cp16cg(T2 + ATB + sw, g_vl + gv);
        }
        cp_commit();
        if (kt < qt) {
            const uint32_t Kn = ((kt + 1) & 1) ? T4 : T0;
            for (int u = tid; u < 1024; u += 256) {
                const int r = u >> 3, c = u & 7;
                const uint32_t sw = swz(r, c);
                const size_t gk = hb + (size_t)((kt + 1) * 128 + r) * HD + c * 8;
                cp16cg(Kn + sw, g_kh + gk);
                cp16cg(Kn + ATB + sw, g_kl + gk);
            }
            cp_commit();
        }

        const uint32_t bKh = (kt & 1) ? T4 : T0;
        const uint32_t bKl = bKh + ATB;

#pragma unroll
        for (int nh = 0; nh < 2; nh++) {
            float sacc[8][4];
#pragma unroll
            for (int nt = 0; nt < 8; nt++)
#pragma unroll
                for (int e = 0; e < 4; e++) sacc[nt][e] = 0.f;

#pragma unroll
            for (int kc = 0; kc < 4; kc++) {
#pragma unroll
                for (int np = 0; np < 2; np++) {
                    uint32_t kh4[2][4], kl4[2][4];
#pragma unroll
                    for (int j = 0; j < 2; j++) {
                        const int krow = (nh * 4 + np * 2 + j) * 16 + b_r;
                        const uint32_t koff = swz(krow, kc * 2 + b_u);
                        ldsm4(kh4[j], bKh + koff);
                        ldsm4(kl4[j], bKl + koff);
                    }
#pragma unroll
                    for (int j = 0; j < 2; j++) {
                        const int n2 = np * 2 + j;
                        mma16816(sacc[2 * n2],     qfh[kc], kh4[j][0], kh4[j][1]);
                        mma16816(sacc[2 * n2 + 1], qfh[kc], kh4[j][2], kh4[j][3]);
                    }
#pragma unroll
                    for (int j = 0; j < 2; j++) {
                        const int n2 = np * 2 + j;
                        mma16816(sacc[2 * n2],     qfh[kc], kl4[j][0], kl4[j][1]);
                        mma16816(sacc[2 * n2 + 1], qfh[kc], kl4[j][2], kl4[j][3]);
                    }
#pragma unroll
                    for (int j = 0; j < 2; j++) {
                        const int n2 = np * 2 + j;
                        mma16816(sacc[2 * n2],     qfl[kc], kh4[j][0], kh4[j][1]);
                        mma16816(sacc[2 * n2 + 1], qfl[kc], kh4[j][2], kh4[j][3]);
                    }
                }
            }

#pragma unroll
            for (int nt = 0; nt < 8; nt++) {
                const int c0 = nh * 64 + nt * 8 + tq * 2;
                const int k0 = kt * 128 + c0;
                const bool v0 = sMask[k0] != 0;
                const bool v1 = sMask[k0 + 1] != 0;
                if (!(v0 && k0     <= row0)) sacc[nt][0] = -1e30f;
                if (!(v1 && k0 + 1 <= row0)) sacc[nt][1] = -1e30f;
                if (!(v0 && k0     <= row1)) sacc[nt][2] = -1e30f;
                if (!(v1 && k0 + 1 <= row1)) sacc[nt][3] = -1e30f;
            }

            float r0 = -1e30f, r1 = -1e30f;
#pragma unroll
            for (int nt = 0; nt < 8; nt++) {
                r0 = fmaxf(r0, fmaxf(sacc[nt][0], sacc[nt][1]));
                r1 = fmaxf(r1, fmaxf(sacc[nt][2], sacc[nt][3]));
            }
            r0 = fmaxf(r0, __shfl_xor_sync(0xffffffffu, r0, 1));
            r0 = fmaxf(r0, __shfl_xor_sync(0xffffffffu, r0, 2));
            r1 = fmaxf(r1, __shfl_xor_sync(0xffffffffu, r1, 1));
            r1 = fmaxf(r1, __shfl_xor_sync(0xffffffffu, r1, 2));

            const float mn0 = fmaxf(m0, r0), mn1 = fmaxf(m1, r1);
            const float al0 = __expf(m0 - mn0), al1 = __expf(m1 - mn1);
            m0 = mn0; m1 = mn1;

            float s0 = 0.f, s1 = 0.f;
#pragma unroll
            for (int nt = 0; nt < 8; nt++) {
                sacc[nt][0] = __expf(sacc[nt][0] - mn0); s0 += sacc[nt][0];
                sacc[nt][1] = __expf(sacc[nt][1] - mn0); s0 += sacc[nt][1];
                sacc[nt][2] = __expf(sacc[nt][2] - mn1); s1 += sacc[nt][2];
                sacc[nt][3] = __expf(sacc[nt][3] - mn1); s1 += sacc[nt][3];
            }
            s0 += __shfl_xor_sync(0xffffffffu, s0, 1);
            s0 += __shfl_xor_sync(0xffffffffu, s0, 2);
            s1 += __shfl_xor_sync(0xffffffffu, s1, 1);
            s1 += __shfl_xor_sync(0xffffffffu, s1, 2);
            l0 = l0 * al0 + s0;
            l1 = l1 * al1 + s1;
#pragma unroll
            for (int nt = 0; nt < 8; nt++) {
                accO[nt][0] *= al0; accO[nt][1] *= al0;
                accO[nt][2] *= al1; accO[nt][3] *= al1;
            }

            if (nh == 0) {
                if (kt < qt) cp_wait<1>(); else cp_wait<0>();
                __syncthreads();
            }

#pragma unroll
            for (int c2l = 0; c2l < 4; c2l++) {
                const int c2 = nh * 4 + c2l;
                const float p00 = sacc[2 * c2l][0],     p01 = sacc[2 * c2l][1];
                const float p02 = sacc[2 * c2l][2],     p03 = sacc[2 * c2l][3];
                const float p10 = sacc[2 * c2l + 1][0], p11 = sacc[2 * c2l + 1][1];
                const float p12 = sacc[2 * c2l + 1][2], p13 = sacc[2 * c2l + 1][3];
                const float h00 = bf16_round(p00), h01 = bf16_round(p01);
                const float h02 = bf16_round(p02), h03 = bf16_round(p03);
                const float h10 = bf16_round(p10), h11 = bf16_round(p11);
                const float h12 = bf16_round(p12), h13 = bf16_round(p13);
                uint32_t ph[4], pl[4];
                ph[0] = pack_bf16(h00, h01); ph[1] = pack_bf16(h02, h03);
                ph[2] = pack_bf16(h10, h11); ph[3] = pack_bf16(h12, h13);
                pl[0] = pack_bf16(p00 - h00, p01 - h01);
                pl[1] = pack_bf16(p02 - h02, p03 - h03);
                pl[2] = pack_bf16(p10 - h10, p11 - h11);
                pl[3] = pack_bf16(p12 - h12, p13 - h13);

#pragma unroll
                for (int dq = 0; dq < 2; dq++) {
                    uint32_t vh4[2][4], vl4[2][4];
#pragma unroll
                    for (int j = 0; j < 2; j++) {
                        const int dp = dq * 2 + j;
                        const int vrow = c2 * 16 + v_kr;
                        const uint32_t voff = swz(vrow, dp * 2 + v_u);
                        ldsm4t(vh4[j], T2 + voff);
                        ldsm4t(vl4[j], T2 + ATB + voff);
                    }
#pragma unroll
                    for (int j = 0; j < 2; j++) {
                        const int dp = dq * 2 + j;
                        mma16816(accO[2 * dp],     ph, vh4[j][0], vh4[j][1]);
                        mma16816(accO[2 * dp + 1], ph, vh4[j][2], vh4[j][3]);
                    }
#pragma unroll
                    for (int j = 0; j < 2; j++) {
                        const int dp = dq * 2 + j;
                        mma16816(accO[2 * dp],     ph, vl4[j][0], vl4[j][1]);
                        mma16816(accO[2 * dp + 1], ph, vl4[j][2], vl4[j][3]);
                    }
#pragma unroll
                    for (int j = 0; j < 2; j++) {
                        const int dp = dq * 2 + j;
                        mma16816(accO[2 * dp],     pl, vh4[j][0], vh4[j][1]);
                        mma16816(accO[2 * dp + 1], pl, vh4[j][2], vh4[j][3]);
                    }
                }
            }
        }
    }

    // ---- epilogue: fp16 hi/lo into [B, S, E] for the fp16 O-projection ----
    const float i0 = 1.f / l0, i1 = 1.f / l1;
    const size_t ob0 = ((size_t)b * SEQ + row0) * EMB + h * HD;
    const size_t ob1 = ((size_t)b * SEQ + row1) * EMB + h * HD;
#pragma unroll
    for (int nt = 0; nt < 8; nt++) {
        const int col = nt * 8 + tq * 2;
        const float x0 = accO[nt][0] * i0, y0 = accO[nt][1] * i0;
        const float x1 = accO[nt][2] * i1, y1 = accO[nt][3] * i1;
        const float hx0 = f16_round(x0), hy0 = f16_round(y0);
        const float hx1 = f16_round(x1), hy1 = f16_round(y1);
        *(uint32_t*)(g_ah + ob0 + col) = pack_f16(hx0, hy0);
        *(uint32_t*)(g_al + ob0 + col) = pack_f16(x0 - hx0, y0 - hy0);
        *(uint32_t*)(g_ah + ob1 + col) = pack_f16(hx1, hy1);
        *(uint32_t*)(g_al + ob1 + col) = pack_f16(x1 - hx1, y1 - hy1);
    }
}

// ---------------------------------------------------------------------------
extern "C" void kernel_launch(void* const* d_in, const int* in_sizes, int n_in,
                              void* d_out, int out_size)
{
    const float* x    = (const float*)d_in[0];
    const int*   mask = (const int*)d_in[1];
    const float* wq   = (const float*)d_in[2];
    const float* wk   = (const float*)d_in[3];
    const float* wv   = (const float*)d_in[4];
    const float* wo   = (const float*)d_in[5];
    float* out = (float*)d_out;

    const int total4 = (MTOT * EMB + 4 * EMB * EMB) / 4;
    split_all_kernel<<<total4 / 256, 256>>>(x, wq, wk, wv, wo);

    cudaFuncSetAttribute(qkv_mma_kernel,
                         cudaFuncAttributeMaxDynamicSharedMemorySize, GEMM_SMEM);
    qkv_mma_kernel<<<dim3(MTOT / 128, EMB / 128, 3), 256, GEMM_SMEM>>>();

    cudaFuncSetAttribute(attn_hmma_kernel,
                         cudaFuncAttributeMaxDynamicSharedMemorySize, ASMEM);
    attn_hmma_kernel<<<dim3(SEQ / 128, NH, NB), 256, ASMEM>>>(mask);

    cudaFuncSetAttribute(oproj_mma_kernel,
                         cudaFuncAttributeMaxDynamicSharedMemorySize, GEMM_SMEM);
    oproj_mma_kernel<<<dim3(MTOT / 128, EMB / 128, 1), 256, GEMM_SMEM>>>(out);
}

// round 15
// speedup vs baseline: 1.9215x; 1.1286x over previous
#include <cuda_runtime.h>
#include <cuda_bf16.h>
#include <cuda_fp16.h>
#include <cstdint>

#define EMB  1024
#define NH   16
#define HD   64
#define SEQ  2048
#define NB   4
#define MTOT (NB * SEQ)   // 8192

// ---------------- scratch (__device__ globals; no allocs allowed) ----------
__device__ __half g_xh[(size_t)MTOT * EMB], g_xl[(size_t)MTOT * EMB];
__device__ __half g_ah[(size_t)MTOT * EMB], g_al[(size_t)MTOT * EMB];
__device__ __half g_wf[4][(size_t)EMB * EMB];
__device__ __half g_qh[(size_t)NB * NH * SEQ * HD], g_ql[(size_t)NB * NH * SEQ * HD];
__device__ __half g_kf[(size_t)NB * NH * SEQ * HD];
__device__ __half g_vf[(size_t)NB * NH * SEQ * HD];

// ---------------- helpers ---------------------------------------------------
__device__ __forceinline__ uint32_t smem_u32(const void* p) {
    uint32_t a;
    asm("{ .reg .u64 t; cvta.to.shared.u64 t, %1; cvt.u32.u64 %0, t; }"
        : "=r"(a) : "l"(p));
    return a;
}
__device__ __forceinline__ void ldsm4(uint32_t* r, uint32_t addr) {
    asm volatile("ldmatrix.sync.aligned.m8n8.x4.shared.b16 {%0,%1,%2,%3}, [%4];"
                 : "=r"(r[0]), "=r"(r[1]), "=r"(r[2]), "=r"(r[3]) : "r"(addr));
}
__device__ __forceinline__ void ldsm4t(uint32_t* r, uint32_t addr) {
    asm volatile("ldmatrix.sync.aligned.m8n8.x4.trans.shared.b16 {%0,%1,%2,%3}, [%4];"
                 : "=r"(r[0]), "=r"(r[1]), "=r"(r[2]), "=r"(r[3]) : "r"(addr));
}
__device__ __forceinline__ void mma16816h(float* c, const uint32_t* a,
                                          uint32_t b0, uint32_t b1) {
    asm volatile(
        "mma.sync.aligned.m16n8k16.row.col.f32.f16.f16.f32 "
        "{%0,%1,%2,%3}, {%4,%5,%6,%7}, {%8,%9}, {%0,%1,%2,%3};"
        : "+f"(c[0]), "+f"(c[1]), "+f"(c[2]), "+f"(c[3])
        : "r"(a[0]), "r"(a[1]), "r"(a[2]), "r"(a[3]), "r"(b0), "r"(b1));
}
__device__ __forceinline__ uint32_t pack_f16(float lo, float hi) {
    uint32_t r;
    asm("cvt.rn.f16x2.f32 %0, %1, %2;" : "=r"(r) : "f"(hi), "f"(lo));
    return r;
}
__device__ __forceinline__ float f16_round(float x) {
    return __half2float(__float2half_rn(x));
}
__device__ __forceinline__ void cp16cg(uint32_t saddr, const void* g) {
    asm volatile("cp.async.cg.shared.global [%0], [%1], 16;"
                 :: "r"(saddr), "l"(g) : "memory");
}
__device__ __forceinline__ void cp16ca(uint32_t saddr, const void* g) {
    asm volatile("cp.async.ca.shared.global [%0], [%1], 16;"
                 :: "r"(saddr), "l"(g) : "memory");
}
__device__ __forceinline__ void cp_commit() {
    asm volatile("cp.async.commit_group;" ::: "memory");
}
template <int N>
__device__ __forceinline__ void cp_wait() {
    asm volatile("cp.async.wait_group %0;" :: "n"(N) : "memory");
}

// ---------------- fused split prepass: x -> fp16 hi/lo, w -> fp16 ------------
__global__ void __launch_bounds__(256)
split_all_kernel(const float* __restrict__ x,
                 const float* __restrict__ wq, const float* __restrict__ wk,
                 const float* __restrict__ wv, const float* __restrict__ wo)
{
    const long long i4 = ((long long)blockIdx.x * 256 + threadIdx.x) * 4;
    if (i4 < (long long)MTOT * EMB) {
        float4 v = *(const float4*)(x + i4);
        float h0 = f16_round(v.x), h1 = f16_round(v.y);
        float h2 = f16_round(v.z), h3 = f16_round(v.w);
        *(uint32_t*)(g_xh + i4)     = pack_f16(h0, h1);
        *(uint32_t*)(g_xh + i4 + 2) = pack_f16(h2, h3);
        *(uint32_t*)(g_xl + i4)     = pack_f16(v.x - h0, v.y - h1);
        *(uint32_t*)(g_xl + i4 + 2) = pack_f16(v.z - h2, v.w - h3);
    } else {
        const long long r = i4 - (long long)MTOT * EMB;
        const int w = (int)(r >> 20);                  // EMB*EMB == 2^20
        const long long off = r & ((1ll << 20) - 1);
        const float* src = (w == 0) ? wq : (w == 1) ? wk : (w == 2) ? wv : wo;
        float4 v = *(const float4*)(src + off);
        *(uint32_t*)(g_wf[w] + off)     = pack_f16(f16_round(v.x), f16_round(v.y));
        *(uint32_t*)(g_wf[w] + off + 2) = pack_f16(f16_round(v.z), f16_round(v.w));
    }
}

// ---------------- fp16 2-MMA split GEMM, cp.async.ca pipeline, 2 CTA/SM ------
// C[m,n] = sum_k A[m,k]*B[n,k]; A split fp16 hi/lo, B single fp16.
// MODE 0: fp32 row-major.  MODE 1: fp16 hi/lo scatter.  MODE 2: fp16 scatter.
#define TS 40
#define TILE_B (128 * TS * 2)          // 10240 B per tile
#define STAGE_B (3 * TILE_B)           // 30720 B per stage (Ah, Al, Bf)
#define GEMM_SMEM (2 * STAGE_B)        // 61440 B -> 2 CTAs/SM

template <int MODE>
__device__ void hmma_gemm(const __half* __restrict__ Ah_,
                          const __half* __restrict__ Al_,
                          const __half* __restrict__ Bf_,
                          float* __restrict__ Cf,
                          __half* __restrict__ Ch,
                          __half* __restrict__ Cl,
                          float oscale)
{
    extern __shared__ char gsm[];
    const uint32_t sb = smem_u32(gsm);

    const int tid   = threadIdx.x;
    const int lane  = tid & 31;
    const int wid   = tid >> 5;
    const int warpM = wid & 3;
    const int warpN = wid >> 2;
    const int m0 = blockIdx.x * 128;
    const int n0 = blockIdx.y * 128;

    const int pr0 = tid >> 1;
    const int pu0 = (tid & 1) << 1;
    const __half* pA0 = Ah_ + (size_t)(m0 + pr0) * EMB + pu0 * 8;
    const __half* pA1 = Al_ + (size_t)(m0 + pr0) * EMB + pu0 * 8;
    const __half* pB0 = Bf_ + (size_t)(n0 + pr0) * EMB + pu0 * 8;
    const uint32_t so = (uint32_t)(pr0 * TS + pu0 * 8) * 2;

    float acc[2][8][4];
#pragma unroll
    for (int mt = 0; mt < 2; mt++)
#pragma unroll
        for (int nt = 0; nt < 8; nt++)
#pragma unroll
            for (int e = 0; e < 4; e++) acc[mt][nt][e] = 0.f;

    const int a_r = lane & 15;
    const int a_c = (lane >> 4) << 3;
    const int b_r = ((lane >> 4) << 3) + (lane & 7);
    const int b_c = ((lane >> 3) & 1) << 3;

    {
        const uint32_t stb = sb;
        cp16ca(stb + so,                   pA0);
        cp16ca(stb + so + 16,              pA0 + 8);
        cp16ca(stb + TILE_B + so,          pA1);
        cp16ca(stb + TILE_B + so + 16,     pA1 + 8);
        cp16ca(stb + 2 * TILE_B + so,      pB0);
        cp16ca(stb + 2 * TILE_B + so + 16, pB0 + 8);
        cp_commit();
    }

    for (int ch = 0; ch < EMB / 32; ch++) {
        const int st = ch & 1;
        cp_wait<0>();
        __syncthreads();
        if (ch + 1 < EMB / 32) {
            const int k1 = (ch + 1) * 32;
            const uint32_t stb = sb + (st ^ 1) * STAGE_B;
            cp16ca(stb + so,                   pA0 + k1);
            cp16ca(stb + so + 16,              pA0 + k1 + 8);
            cp16ca(stb + TILE_B + so,          pA1 + k1);
            cp16ca(stb + TILE_B + so + 16,     pA1 + k1 + 8);
            cp16ca(stb + 2 * TILE_B + so,      pB0 + k1);
            cp16ca(stb + 2 * TILE_B + so + 16, pB0 + k1 + 8);
            cp_commit();
        }

        const uint32_t stb = sb + st * STAGE_B;
        const uint32_t bAh = stb;
        const uint32_t bAl = stb + TILE_B;
        const uint32_t bBf = stb + 2 * TILE_B;

#pragma unroll
        for (int ks = 0; ks < 2; ks++) {
            const int kb = ks << 4;
            uint32_t ah[2][4], al[2][4];
#pragma unroll
            for (int mt = 0; mt < 2; mt++) {
                const uint32_t off =
                    (uint32_t)((warpM * 32 + mt * 16 + a_r) * TS + kb + a_c) * 2;
                ldsm4(ah[mt], bAh + off);
                ldsm4(al[mt], bAl + off);
            }
#pragma unroll
            for (int ng = 0; ng < 4; ng++) {
                const uint32_t off =
                    (uint32_t)((warpN * 64 + ng * 16 + b_r) * TS + kb + b_c) * 2;
                uint32_t bf[4];
                ldsm4(bf, bBf + off);
#pragma unroll
                for (int mt = 0; mt < 2; mt++) {        // pass hi
                    mma16816h(acc[mt][2 * ng],     ah[mt], bf[0], bf[1]);
                    mma16816h(acc[mt][2 * ng + 1], ah[mt], bf[2], bf[3]);
                }
#pragma unroll
                for (int mt = 0; mt < 2; mt++) {        // pass lo
                    mma16816h(acc[mt][2 * ng],     al[mt], bf[0], bf[1]);
                    mma16816h(acc[mt][2 * ng + 1], al[mt], bf[2], bf[3]);
                }
            }
        }
    }

#pragma unroll
    for (int mt = 0; mt < 2; mt++) {
#pragma unroll
        for (int nt = 0; nt < 8; nt++) {
            const int row = m0 + warpM * 32 + mt * 16 + (lane >> 2);
            const int col = n0 + warpN * 64 + nt * 8 + ((lane & 3) << 1);
#pragma unroll
            for (int half = 0; half < 2; half++) {
                const int r = row + half * 8;
                float vx = acc[mt][nt][2 * half]     * oscale;
                float vy = acc[mt][nt][2 * half + 1] * oscale;
                if (MODE == 0) {
                    *(float2*)&Cf[(size_t)r * EMB + col] = make_float2(vx, vy);
                } else {
                    const int b = r >> 11, s = r & (SEQ - 1);
                    const int h = col >> 6, d = col & (HD - 1);
                    const size_t o = ((((size_t)b * NH + h) * SEQ + s) << 6) + d;
                    if (MODE == 1) {
                        float hx = f16_round(vx), hy = f16_round(vy);
                        *(uint32_t*)(Ch + o) = pack_f16(hx, hy);
                        *(uint32_t*)(Cl + o) = pack_f16(vx - hx, vy - hy);
                    } else {
                        *(uint32_t*)(Ch + o) = pack_f16(f16_round(vx), f16_round(vy));
                    }
                }
            }
        }
    }
}

__global__ void __launch_bounds__(256, 2) qkv_mma_kernel()
{
    const int z = blockIdx.z;
    if (z == 0)
        hmma_gemm<1>(g_xh, g_xl, g_wf[0], nullptr, g_qh, g_ql, 0.125f);
    else if (z == 1)
        hmma_gemm<2>(g_xh, g_xl, g_wf[1], nullptr, g_kf, nullptr, 1.0f);
    else
        hmma_gemm<2>(g_xh, g_xl, g_wf[2], nullptr, g_vf, nullptr, 1.0f);
}
__global__ void __launch_bounds__(256, 2) oproj_mma_kernel(float* __restrict__ out)
{
    hmma_gemm<0>(g_ah, g_al, g_wf[3], out, nullptr, nullptr, 1.0f);
}

// ---------------- fp16 2-MMA flash attention ---------------------------------
// QK: Qh*K + Ql*K (Q split fp16 in regs, K single fp16).
// PV: Ph*V + Pl*V (P split fp16, V single fp16).
// Tiles: T0 = K stage0, T2 = V (Qh preload), T4 = Q lo preload -> K stage1.
#define ATB 16384
#define ASMEM (3 * ATB + SEQ * 4)    // 57344 B

__device__ __forceinline__ uint32_t swz(int r, int u) {
    return (uint32_t)(r * 128 + (((u ^ r) & 7) << 4) + (u & ~7) * 16);
}

__global__ void __launch_bounds__(256, 2)
attn_hmma_kernel(const int* __restrict__ mask)
{
    extern __shared__ char sm[];
    const uint32_t T0 = smem_u32(sm);
    const uint32_t T2 = T0 + ATB;
    const uint32_t T4 = T0 + 2 * ATB;
    int* sMask = (int*)(sm + 3 * ATB);

    const int tid  = threadIdx.x;
    const int lane = tid & 31;
    const int wid  = tid >> 5;
    const int qt   = blockIdx.x;
    const int h    = blockIdx.y;
    const int b    = blockIdx.z;

    const size_t hb = ((size_t)b * NH + h) * SEQ * HD;
    const int* mrow = mask + b * SEQ;

    // preload: Qh -> T2 (temp), Ql -> T4 (temp), K(0) -> T0, mask row
    for (int u = tid; u < 1024; u += 256) {
        const int r = u >> 3, c = u & 7;
        const uint32_t sw = swz(r, c);
        const size_t gq = hb + (size_t)(qt * 128 + r) * HD + c * 8;
        const size_t gk = hb + (size_t)r * HD + c * 8;
        cp16cg(T2 + sw, g_qh + gq);
        cp16cg(T4 + sw, g_ql + gq);
        cp16cg(T0 + sw, g_kf + gk);
    }
    for (int i = tid; i < SEQ; i += 256) sMask[i] = mrow[i];
    cp_commit();
    cp_wait<0>();
    __syncthreads();

    const int a_r = lane & 15;
    const int a_u = lane >> 4;
    const int b_r = ((lane >> 4) << 3) + (lane & 7);
    const int b_u = (lane >> 3) & 1;
    const int v_kr = ((lane >> 3) & 1) * 8 + (lane & 7);
    const int v_u  = lane >> 4;

    const int tq   = lane & 3;
    const int row0 = qt * 128 + wid * 16 + (lane >> 2);
    const int row1 = row0 + 8;
    const int qrow = wid * 16 + a_r;

    // hoist Q fragments (fp16 hi/lo) into registers
    uint32_t qfh[4][4], qfl[4][4];
#pragma unroll
    for (int kc = 0; kc < 4; kc++) {
        const uint32_t qoff = swz(qrow, kc * 2 + a_u);
        ldsm4(qfh[kc], T2 + qoff);
        ldsm4(qfl[kc], T4 + qoff);
    }
    __syncthreads();    // T2 -> V tile, T4 -> K stage1

    float m0 = -1e30f, m1 = -1e30f, l0 = 0.f, l1 = 0.f;
    float accO[8][4];
#pragma unroll
    for (int nt = 0; nt < 8; nt++)
#pragma unroll
        for (int e = 0; e < 4; e++) accO[nt][e] = 0.f;

    for (int kt = 0; kt <= qt; kt++) {
        if (kt > 0) {
            cp_wait<0>();        // K(kt) landed
            __syncthreads();     // PV(kt-1) done -> V overwrite safe
        }

        // issue V(kt) (overlaps QK+softmax)
        for (int u = tid; u < 1024; u += 256) {
            const int r = u >> 3, c = u & 7;
            cp16cg(T2 + swz(r, c), g_vf + hb + (size_t)(kt * 128 + r) * HD + c * 8);
        }
        cp_commit();
        // issue K(kt+1) into the other stage (overlaps QK+PV)
        if (kt < qt) {
            const uint32_t Kn = ((kt + 1) & 1) ? T4 : T0;
            for (int u = tid; u < 1024; u += 256) {
                const int r = u >> 3, c = u & 7;
                cp16cg(Kn + swz(r, c),
                       g_kf + hb + (size_t)((kt + 1) * 128 + r) * HD + c * 8);
            }
            cp_commit();
        }

        const uint32_t bKf = (kt & 1) ? T4 : T0;

#pragma unroll
        for (int nh = 0; nh < 2; nh++) {
            float sacc[8][4];
#pragma unroll
            for (int nt = 0; nt < 8; nt++)
#pragma unroll
                for (int e = 0; e < 4; e++) sacc[nt][e] = 0.f;

#pragma unroll
            for (int kc = 0; kc < 4; kc++) {
#pragma unroll
                for (int np = 0; np < 2; np++) {
                    uint32_t kf4[2][4];
#pragma unroll
                    for (int j = 0; j < 2; j++) {
                        const int krow = (nh * 4 + np * 2 + j) * 16 + b_r;
                        ldsm4(kf4[j], bKf + swz(krow, kc * 2 + b_u));
                    }
#pragma unroll
                    for (int j = 0; j < 2; j++) {       // pass hi
                        const int n2 = np * 2 + j;
                        mma16816h(sacc[2 * n2],     qfh[kc], kf4[j][0], kf4[j][1]);
                        mma16816h(sacc[2 * n2 + 1], qfh[kc], kf4[j][2], kf4[j][3]);
                    }
#pragma unroll
                    for (int j = 0; j < 2; j++) {       // pass lo
                        const int n2 = np * 2 + j;
                        mma16816h(sacc[2 * n2],     qfl[kc], kf4[j][0], kf4[j][1]);
                        mma16816h(sacc[2 * n2 + 1], qfl[kc], kf4[j][2], kf4[j][3]);
                    }
                }
            }

#pragma unroll
            for (int nt = 0; nt < 8; nt++) {
                const int c0 = nh * 64 + nt * 8 + tq * 2;
                const int k0 = kt * 128 + c0;
                const bool v0 = sMask[k0] != 0;
                const bool v1 = sMask[k0 + 1] != 0;
                if (!(v0 && k0     <= row0)) sacc[nt][0] = -1e30f;
                if (!(v1 && k0 + 1 <= row0)) sacc[nt][1] = -1e30f;
                if (!(v0 && k0     <= row1)) sacc[nt][2] = -1e30f;
                if (!(v1 && k0 + 1 <= row1)) sacc[nt][3] = -1e30f;
            }

            float r0 = -1e30f, r1 = -1e30f;
#pragma unroll
            for (int nt = 0; nt < 8; nt++) {
                r0 = fmaxf(r0, fmaxf(sacc[nt][0], sacc[nt][1]));
                r1 = fmaxf(r1, fmaxf(sacc[nt][2], sacc[nt][3]));
            }
            r0 = fmaxf(r0, __shfl_xor_sync(0xffffffffu, r0, 1));
            r0 = fmaxf(r0, __shfl_xor_sync(0xffffffffu, r0, 2));
            r1 = fmaxf(r1, __shfl_xor_sync(0xffffffffu, r1, 1));
            r1 = fmaxf(r1, __shfl_xor_sync(0xffffffffu, r1, 2));

            const float mn0 = fmaxf(m0, r0), mn1 = fmaxf(m1, r1);
            const float al0 = __expf(m0 - mn0), al1 = __expf(m1 - mn1);
            m0 = mn0; m1 = mn1;

            float s0 = 0.f, s1 = 0.f;
#pragma unroll
            for (int nt = 0; nt < 8; nt++) {
                sacc[nt][0] = __expf(sacc[nt][0] - mn0); s0 += sacc[nt][0];
                sacc[nt][1] = __expf(sacc[nt][1] - mn0); s0 += sacc[nt][1];
                sacc[nt][2] = __expf(sacc[nt][2] - mn1); s1 += sacc[nt][2];
                sacc[nt][3] = __expf(sacc[nt][3] - mn1); s1 += sacc[nt][3];
            }
            s0 += __shfl_xor_sync(0xffffffffu, s0, 1);
            s0 += __shfl_xor_sync(0xffffffffu, s0, 2);
            s1 += __shfl_xor_sync(0xffffffffu, s1, 1);
            s1 += __shfl_xor_sync(0xffffffffu, s1, 2);
            l0 = l0 * al0 + s0;
            l1 = l1 * al1 + s1;
#pragma unroll
            for (int nt = 0; nt < 8; nt++) {
                accO[nt][0] *= al0; accO[nt][1] *= al0;
                accO[nt][2] *= al1; accO[nt][3] *= al1;
            }

            if (nh == 0) {
                // V must be resident before the first PV half
                if (kt < qt) cp_wait<1>(); else cp_wait<0>();
                __syncthreads();
            }

#pragma unroll
            for (int c2l = 0; c2l < 4; c2l++) {
                const int c2 = nh * 4 + c2l;
                const float p00 = sacc[2 * c2l][0],     p01 = sacc[2 * c2l][1];
                const float p02 = sacc[2 * c2l][2],     p03 = sacc[2 * c2l][3];
                const float p10 = sacc[2 * c2l + 1][0], p11 = sacc[2 * c2l + 1][1];
                const float p12 = sacc[2 * c2l + 1][2], p13 = sacc[2 * c2l + 1][3];
                const float h00 = f16_round(p00), h01 = f16_round(p01);
                const float h02 = f16_round(p02), h03 = f16_round(p03);
                const float h10 = f16_round(p10), h11 = f16_round(p11);
                const float h12 = f16_round(p12), h13 = f16_round(p13);
                uint32_t ph[4], pl[4];
                ph[0] = pack_f16(h00, h01); ph[1] = pack_f16(h02, h03);
                ph[2] = pack_f16(h10, h11); ph[3] = pack_f16(h12, h13);
                pl[0] = pack_f16(p00 - h00, p01 - h01);
                pl[1] = pack_f16(p02 - h02, p03 - h03);
                pl[2] = pack_f16(p10 - h10, p11 - h11);
                pl[3] = pack_f16(p12 - h12, p13 - h13);

#pragma unroll
                for (int dq = 0; dq < 2; dq++) {
                    uint32_t vf4[2][4];
#pragma unroll
                    for (int j = 0; j < 2; j++) {
                        const int dp = dq * 2 + j;
                        const int vrow = c2 * 16 + v_kr;
                        ldsm4t(vf4[j], T2 + swz(vrow, dp * 2 + v_u));
                    }
#pragma unroll
                    for (int j = 0; j < 2; j++) {       // pass hi
                        const int dp = dq * 2 + j;
                        mma16816h(accO[2 * dp],     ph, vf4[j][0], vf4[j][1]);
                        mma16816h(accO[2 * dp + 1], ph, vf4[j][2], vf4[j][3]);
                    }
#pragma unroll
                    for (int j = 0; j < 2; j++) {       // pass lo
                        const int dp = dq * 2 + j;
                        mma16816h(accO[2 * dp],     pl, vf4[j][0], vf4[j][1]);
                        mma16816h(accO[2 * dp + 1], pl, vf4[j][2], vf4[j][3]);
                    }
                }
            }
        }
    }

    // ---- epilogue: fp16 hi/lo into [B, S, E] for the fp16 O-projection ----
    const float i0 = 1.f / l0, i1 = 1.f / l1;
    const size_t ob0 = ((size_t)b * SEQ + row0) * EMB + h * HD;
    const size_t ob1 = ((size_t)b * SEQ + row1) * EMB + h * HD;
#pragma unroll
    for (int nt = 0; nt < 8; nt++) {
        const int col = nt * 8 + tq * 2;
        const float x0 = accO[nt][0] * i0, y0 = accO[nt][1] * i0;
        const float x1 = accO[nt][2] * i1, y1 = accO[nt][3] * i1;
        const float hx0 = f16_round(x0), hy0 = f16_round(y0);
        const float hx1 = f16_round(x1), hy1 = f16_round(y1);
        *(uint32_t*)(g_ah + ob0 + col) = pack_f16(hx0, hy0);
        *(uint32_t*)(g_al + ob0 + col) = pack_f16(x0 - hx0, y0 - hy0);
        *(uint32_t*)(g_ah + ob1 + col) = pack_f16(hx1, hy1);
        *(uint32_t*)(g_al + ob1 + col) = pack_f16(x1 - hx1, y1 - hy1);
    }
}

// ---------------------------------------------------------------------------
extern "C" void kernel_launch(void* const* d_in, const int* in_sizes, int n_in,
                              void* d_out, int out_size)
{
    const float* x    = (const float*)d_in[0];
    const int*   mask = (const int*)d_in[1];
    const float* wq   = (const float*)d_in[2];
    const float* wk   = (const float*)d_in[3];
    const float* wv   = (const float*)d_in[4];
    const float* wo   = (const float*)d_in[5];
    float* out = (float*)d_out;

    const int total4 = (MTOT * EMB + 4 * EMB * EMB) / 4;
    split_all_kernel<<<total4 / 256, 256>>>(x, wq, wk, wv, wo);

    cudaFuncSetAttribute(qkv_mma_kernel,
                         cudaFuncAttributeMaxDynamicSharedMemorySize, GEMM_SMEM);
    qkv_mma_kernel<<<dim3(MTOT / 128, EMB / 128, 3), 256, GEMM_SMEM>>>();

    cudaFuncSetAttribute(attn_hmma_kernel,
                         cudaFuncAttributeMaxDynamicSharedMemorySize, ASMEM);
    attn_hmma_kernel<<<dim3(SEQ / 128, NH, NB), 256, ASMEM>>>(mask);

    cudaFuncSetAttribute(oproj_mma_kernel,
                         cudaFuncAttributeMaxDynamicSharedMemorySize, GEMM_SMEM);
    oproj_mma_kernel<<<dim3(MTOT / 128, EMB / 128, 1), 256, GEMM_SMEM>>>(out);
}

// round 16
// speedup vs baseline: 2.5212x; 1.3121x over previous
#include <cuda_runtime.h>
#include <cuda_bf16.h>
#include <cuda_fp16.h>
#include <cstdint>

#define EMB  1024
#define NH   16
#define HD   64
#define SEQ  2048
#define NB   4
#define MTOT (NB * SEQ)   // 8192

// ---------------- scratch (__device__ globals; no allocs allowed) ----------
__device__ __half g_xf[(size_t)MTOT * EMB];
__device__ __half g_af[(size_t)MTOT * EMB];
__device__ __half g_wf[4][(size_t)EMB * EMB];
__device__ __half g_qh[(size_t)NB * NH * SEQ * HD], g_ql[(size_t)NB * NH * SEQ * HD];
__device__ __half g_kf[(size_t)NB * NH * SEQ * HD];
__device__ __half g_vf[(size_t)NB * NH * SEQ * HD];

// ---------------- helpers ---------------------------------------------------
__device__ __forceinline__ uint32_t smem_u32(const void* p) {
    uint32_t a;
    asm("{ .reg .u64 t; cvta.to.shared.u64 t, %1; cvt.u32.u64 %0, t; }"
        : "=r"(a) : "l"(p));
    return a;
}
__device__ __forceinline__ void ldsm4(uint32_t* r, uint32_t addr) {
    asm volatile("ldmatrix.sync.aligned.m8n8.x4.shared.b16 {%0,%1,%2,%3}, [%4];"
                 : "=r"(r[0]), "=r"(r[1]), "=r"(r[2]), "=r"(r[3]) : "r"(addr));
}
__device__ __forceinline__ void ldsm4t(uint32_t* r, uint32_t addr) {
    asm volatile("ldmatrix.sync.aligned.m8n8.x4.trans.shared.b16 {%0,%1,%2,%3}, [%4];"
                 : "=r"(r[0]), "=r"(r[1]), "=r"(r[2]), "=r"(r[3]) : "r"(addr));
}
__device__ __forceinline__ void mma16816h(float* c, const uint32_t* a,
                                          uint32_t b0, uint32_t b1) {
    asm volatile(
        "mma.sync.aligned.m16n8k16.row.col.f32.f16.f16.f32 "
        "{%0,%1,%2,%3}, {%4,%5,%6,%7}, {%8,%9}, {%0,%1,%2,%3};"
        : "+f"(c[0]), "+f"(c[1]), "+f"(c[2]), "+f"(c[3])
        : "r"(a[0]), "r"(a[1]), "r"(a[2]), "r"(a[3]), "r"(b0), "r"(b1));
}
__device__ __forceinline__ uint32_t pack_f16(float lo, float hi) {
    uint32_t r;
    asm("cvt.rn.f16x2.f32 %0, %1, %2;" : "=r"(r) : "f"(hi), "f"(lo));
    return r;
}
__device__ __forceinline__ float f16_round(float x) {
    return __half2float(__float2half_rn(x));
}
__device__ __forceinline__ void cp16cg(uint32_t saddr, const void* g) {
    asm volatile("cp.async.cg.shared.global [%0], [%1], 16;"
                 :: "r"(saddr), "l"(g) : "memory");
}
__device__ __forceinline__ void cp16ca(uint32_t saddr, const void* g) {
    asm volatile("cp.async.ca.shared.global [%0], [%1], 16;"
                 :: "r"(saddr), "l"(g) : "memory");
}
__device__ __forceinline__ void cp_commit() {
    asm volatile("cp.async.commit_group;" ::: "memory");
}
template <int N>
__device__ __forceinline__ void cp_wait() {
    asm volatile("cp.async.wait_group %0;" :: "n"(N) : "memory");
}

// ---------------- fused split prepass: x, w -> single fp16 -------------------
__global__ void __launch_bounds__(256)
split_all_kernel(const float* __restrict__ x,
                 const float* __restrict__ wq, const float* __restrict__ wk,
                 const float* __restrict__ wv, const float* __restrict__ wo)
{
    const long long i4 = ((long long)blockIdx.x * 256 + threadIdx.x) * 4;
    const float* src;
    __half* dst;
    long long off;
    if (i4 < (long long)MTOT * EMB) {
        src = x; dst = g_xf; off = i4;
    } else {
        const long long r = i4 - (long long)MTOT * EMB;
        const int w = (int)(r >> 20);                  // EMB*EMB == 2^20
        off = r & ((1ll << 20) - 1);
        src = (w == 0) ? wq : (w == 1) ? wk : (w == 2) ? wv : wo;
        dst = g_wf[w];
    }
    float4 v = *(const float4*)(src + off);
    *(uint32_t*)(dst + off)     = pack_f16(v.x, v.y);
    *(uint32_t*)(dst + off + 2) = pack_f16(v.z, v.w);
}

// ---------------- fp16 single-MMA GEMM, cp.async.ca pipeline, 2 CTA/SM -------
// C[m,n] = sum_k A[m,k]*B[n,k]; both single fp16, fp32 accumulate.
// MODE 0: fp32 row-major.  MODE 1: fp16 hi/lo scatter (Q).  MODE 2: fp16 scatter.
#define TS 40
#define TILE_B (128 * TS * 2)          // 10240 B per tile
#define STAGE_B (2 * TILE_B)           // 20480 B per stage (Af, Bf)
#define GEMM_SMEM (2 * STAGE_B)        // 40960 B

template <int MODE>
__device__ void hmma_gemm(const __half* __restrict__ Af_,
                          const __half* __restrict__ Bf_,
                          float* __restrict__ Cf,
                          __half* __restrict__ Ch,
                          __half* __restrict__ Cl,
                          float oscale)
{
    extern __shared__ char gsm[];
    const uint32_t sb = smem_u32(gsm);

    const int tid   = threadIdx.x;
    const int lane  = tid & 31;
    const int wid   = tid >> 5;
    const int warpM = wid & 3;
    const int warpN = wid >> 2;
    const int m0 = blockIdx.x * 128;
    const int n0 = blockIdx.y * 128;

    const int pr0 = tid >> 1;
    const int pu0 = (tid & 1) << 1;
    const __half* pA0 = Af_ + (size_t)(m0 + pr0) * EMB + pu0 * 8;
    const __half* pB0 = Bf_ + (size_t)(n0 + pr0) * EMB + pu0 * 8;
    const uint32_t so = (uint32_t)(pr0 * TS + pu0 * 8) * 2;

    float acc[2][8][4];
#pragma unroll
    for (int mt = 0; mt < 2; mt++)
#pragma unroll
        for (int nt = 0; nt < 8; nt++)
#pragma unroll
            for (int e = 0; e < 4; e++) acc[mt][nt][e] = 0.f;

    const int a_r = lane & 15;
    const int a_c = (lane >> 4) << 3;
    const int b_r = ((lane >> 4) << 3) + (lane & 7);
    const int b_c = ((lane >> 3) & 1) << 3;

    {
        const uint32_t stb = sb;
        cp16ca(stb + so,               pA0);
        cp16ca(stb + so + 16,          pA0 + 8);
        cp16ca(stb + TILE_B + so,      pB0);
        cp16ca(stb + TILE_B + so + 16, pB0 + 8);
        cp_commit();
    }

    for (int ch = 0; ch < EMB / 32; ch++) {
        const int st = ch & 1;
        cp_wait<0>();
        __syncthreads();
        if (ch + 1 < EMB / 32) {
            const int k1 = (ch + 1) * 32;
            const uint32_t stb = sb + (st ^ 1) * STAGE_B;
            cp16ca(stb + so,               pA0 + k1);
            cp16ca(stb + so + 16,          pA0 + k1 + 8);
            cp16ca(stb + TILE_B + so,      pB0 + k1);
            cp16ca(stb + TILE_B + so + 16, pB0 + k1 + 8);
            cp_commit();
        }

        const uint32_t stb = sb + st * STAGE_B;
        const uint32_t bAf = stb;
        const uint32_t bBf = stb + TILE_B;

#pragma unroll
        for (int ks = 0; ks < 2; ks++) {
            const int kb = ks << 4;
            uint32_t af[2][4];
#pragma unroll
            for (int mt = 0; mt < 2; mt++) {
                const uint32_t off =
                    (uint32_t)((warpM * 32 + mt * 16 + a_r) * TS + kb + a_c) * 2;
                ldsm4(af[mt], bAf + off);
            }
#pragma unroll
            for (int ng = 0; ng < 4; ng++) {
                const uint32_t off =
                    (uint32_t)((warpN * 64 + ng * 16 + b_r) * TS + kb + b_c) * 2;
                uint32_t bf[4];
                ldsm4(bf, bBf + off);
#pragma unroll
                for (int mt = 0; mt < 2; mt++) {
                    mma16816h(acc[mt][2 * ng],     af[mt], bf[0], bf[1]);
                    mma16816h(acc[mt][2 * ng + 1], af[mt], bf[2], bf[3]);
                }
            }
        }
    }

#pragma unroll
    for (int mt = 0; mt < 2; mt++) {
#pragma unroll
        for (int nt = 0; nt < 8; nt++) {
            const int row = m0 + warpM * 32 + mt * 16 + (lane >> 2);
            const int col = n0 + warpN * 64 + nt * 8 + ((lane & 3) << 1);
#pragma unroll
            for (int half = 0; half < 2; half++) {
                const int r = row + half * 8;
                float vx = acc[mt][nt][2 * half]     * oscale;
                float vy = acc[mt][nt][2 * half + 1] * oscale;
                if (MODE == 0) {
                    *(float2*)&Cf[(size_t)r * EMB + col] = make_float2(vx, vy);
                } else {
                    const int b = r >> 11, s = r & (SEQ - 1);
                    const int h = col >> 6, d = col & (HD - 1);
                    const size_t o = ((((size_t)b * NH + h) * SEQ + s) << 6) + d;
                    if (MODE == 1) {
                        float hx = f16_round(vx), hy = f16_round(vy);
                        *(uint32_t*)(Ch + o) = pack_f16(hx, hy);
                        *(uint32_t*)(Cl + o) = pack_f16(vx - hx, vy - hy);
                    } else {
                        *(uint32_t*)(Ch + o) = pack_f16(vx, vy);
                    }
                }
            }
        }
    }
}

__global__ void __launch_bounds__(256, 2) qkv_mma_kernel()
{
    const int z = blockIdx.z;
    if (z == 0)
        hmma_gemm<1>(g_xf, g_wf[0], nullptr, g_qh, g_ql, 0.125f);
    else if (z == 1)
        hmma_gemm<2>(g_xf, g_wf[1], nullptr, g_kf, nullptr, 1.0f);
    else
        hmma_gemm<2>(g_xf, g_wf[2], nullptr, g_vf, nullptr, 1.0f);
}
__global__ void __launch_bounds__(256, 2) oproj_mma_kernel(float* __restrict__ out)
{
    hmma_gemm<0>(g_af, g_wf[3], out, nullptr, nullptr, 1.0f);
}

// ---------------- fp16 flash attention ---------------------------------------
// QK: Qh*K + Ql*K (Q split fp16 in regs, K single fp16) — softmax-critical.
// PV: P*V single pass (both post-softmax-safe fp16).
// Tiles: T0 = K stage0, T2 = V (Qh preload), T4 = Ql preload -> K stage1.
#define ATB 16384
#define ASMEM (3 * ATB + SEQ * 4)    // 57344 B

__device__ __forceinline__ uint32_t swz(int r, int u) {
    return (uint32_t)(r * 128 + (((u ^ r) & 7) << 4) + (u & ~7) * 16);
}

__global__ void __launch_bounds__(256, 2)
attn_hmma_kernel(const int* __restrict__ mask)
{
    extern __shared__ char sm[];
    const uint32_t T0 = smem_u32(sm);
    const uint32_t T2 = T0 + ATB;
    const uint32_t T4 = T0 + 2 * ATB;
    int* sMask = (int*)(sm + 3 * ATB);

    const int tid  = threadIdx.x;
    const int lane = tid & 31;
    const int wid  = tid >> 5;
    const int qt   = blockIdx.x;
    const int h    = blockIdx.y;
    const int b    = blockIdx.z;

    const size_t hb = ((size_t)b * NH + h) * SEQ * HD;
    const int* mrow = mask + b * SEQ;

    for (int u = tid; u < 1024; u += 256) {
        const int r = u >> 3, c = u & 7;
        const uint32_t sw = swz(r, c);
        const size_t gq = hb + (size_t)(qt * 128 + r) * HD + c * 8;
        const size_t gk = hb + (size_t)r * HD + c * 8;
        cp16cg(T2 + sw, g_qh + gq);
        cp16cg(T4 + sw, g_ql + gq);
        cp16cg(T0 + sw, g_kf + gk);
    }
    for (int i = tid; i < SEQ; i += 256) sMask[i] = mrow[i];
    cp_commit();
    cp_wait<0>();
    __syncthreads();

    const int a_r = lane & 15;
    const int a_u = lane >> 4;
    const int b_r = ((lane >> 4) << 3) + (lane & 7);
    const int b_u = (lane >> 3) & 1;
    const int v_kr = ((lane >> 3) & 1) * 8 + (lane & 7);
    const int v_u  = lane >> 4;

    const int tq   = lane & 3;
    const int row0 = qt * 128 + wid * 16 + (lane >> 2);
    const int row1 = row0 + 8;
    const int qrow = wid * 16 + a_r;

    uint32_t qfh[4][4], qfl[4][4];
#pragma unroll
    for (int kc = 0; kc < 4; kc++) {
        const uint32_t qoff = swz(qrow, kc * 2 + a_u);
        ldsm4(qfh[kc], T2 + qoff);
        ldsm4(qfl[kc], T4 + qoff);
    }
    __syncthreads();    // T2 -> V tile, T4 -> K stage1

    float m0 = -1e30f, m1 = -1e30f, l0 = 0.f, l1 = 0.f;
    float accO[8][4];
#pragma unroll
    for (int nt = 0; nt < 8; nt++)
#pragma unroll
        for (int e = 0; e < 4; e++) accO[nt][e] = 0.f;

    for (int kt = 0; kt <= qt; kt++) {
        if (kt > 0) {
            cp_wait<0>();
            __syncthreads();
        }

        for (int u = tid; u < 1024; u += 256) {
            const int r = u >> 3, c = u & 7;
            cp16cg(T2 + swz(r, c), g_vf + hb + (size_t)(kt * 128 + r) * HD + c * 8);
        }
        cp_commit();
        if (kt < qt) {
            const uint32_t Kn = ((kt + 1) & 1) ? T4 : T0;
            for (int u = tid; u < 1024; u += 256) {
                const int r = u >> 3, c = u & 7;
                cp16cg(Kn + swz(r, c),
                       g_kf + hb + (size_t)((kt + 1) * 128 + r) * HD + c * 8);
            }
            cp_commit();
        }

        const uint32_t bKf = (kt & 1) ? T4 : T0;

#pragma unroll
        for (int nh = 0; nh < 2; nh++) {
            float sacc[8][4];
#pragma unroll
            for (int nt = 0; nt < 8; nt++)
#pragma unroll
                for (int e = 0; e < 4; e++) sacc[nt][e] = 0.f;

#pragma unroll
            for (int kc = 0; kc < 4; kc++) {
#pragma unroll
                for (int np = 0; np < 2; np++) {
                    uint32_t kf4[2][4];
#pragma unroll
                    for (int j = 0; j < 2; j++) {
                        const int krow = (nh * 4 + np * 2 + j) * 16 + b_r;
                        ldsm4(kf4[j], bKf + swz(krow, kc * 2 + b_u));
                    }
#pragma unroll
                    for (int j = 0; j < 2; j++) {       // pass hi
                        const int n2 = np * 2 + j;
                        mma16816h(sacc[2 * n2],     qfh[kc], kf4[j][0], kf4[j][1]);
                        mma16816h(sacc[2 * n2 + 1], qfh[kc], kf4[j][2], kf4[j][3]);
                    }
#pragma unroll
                    for (int j = 0; j < 2; j++) {       // pass lo
                        const int n2 = np * 2 + j;
                        mma16816h(sacc[2 * n2],     qfl[kc], kf4[j][0], kf4[j][1]);
                        mma16816h(sacc[2 * n2 + 1], qfl[kc], kf4[j][2], kf4[j][3]);
                    }
                }
            }

#pragma unroll
            for (int nt = 0; nt < 8; nt++) {
                const int c0 = nh * 64 + nt * 8 + tq * 2;
                const int k0 = kt * 128 + c0;
                const bool v0 = sMask[k0] != 0;
                const bool v1 = sMask[k0 + 1] != 0;
                if (!(v0 && k0     <= row0)) sacc[nt][0] = -1e30f;
                if (!(v1 && k0 + 1 <= row0)) sacc[nt][1] = -1e30f;
                if (!(v0 && k0     <= row1)) sacc[nt][2] = -1e30f;
                if (!(v1 && k0 + 1 <= row1)) sacc[nt][3] = -1e30f;
            }

            float r0 = -1e30f, r1 = -1e30f;
#pragma unroll
            for (int nt = 0; nt < 8; nt++) {
                r0 = fmaxf(r0, fmaxf(sacc[nt][0], sacc[nt][1]));
                r1 = fmaxf(r1, fmaxf(sacc[nt][2], sacc[nt][3]));
            }
            r0 = fmaxf(r0, __shfl_xor_sync(0xffffffffu, r0, 1));
            r0 = fmaxf(r0, __shfl_xor_sync(0xffffffffu, r0, 2));
            r1 = fmaxf(r1, __shfl_xor_sync(0xffffffffu, r1, 1));
            r1 = fmaxf(r1, __shfl_xor_sync(0xffffffffu, r1, 2));

            const float mn0 = fmaxf(m0, r0), mn1 = fmaxf(m1, r1);
            const float al0 = __expf(m0 - mn0), al1 = __expf(m1 - mn1);
            m0 = mn0; m1 = mn1;

            float s0 = 0.f, s1 = 0.f;
#pragma unroll
            for (int nt = 0; nt < 8; nt++) {
                sacc[nt][0] = __expf(sacc[nt][0] - mn0); s0 += sacc[nt][0];
                sacc[nt][1] = __expf(sacc[nt][1] - mn0); s0 += sacc[nt][1];
                sacc[nt][2] = __expf(sacc[nt][2] - mn1); s1 += sacc[nt][2];
                sacc[nt][3] = __expf(sacc[nt][3] - mn1); s1 += sacc[nt][3];
            }
            s0 += __shfl_xor_sync(0xffffffffu, s0, 1);
            s0 += __shfl_xor_sync(0xffffffffu, s0, 2);
            s1 += __shfl_xor_sync(0xffffffffu, s1, 1);
            s1 += __shfl_xor_sync(0xffffffffu, s1, 2);
            l0 = l0 * al0 + s0;
            l1 = l1 * al1 + s1;
#pragma unroll
            for (int nt = 0; nt < 8; nt++) {
                accO[nt][0] *= al0; accO[nt][1] *= al0;
                accO[nt][2] *= al1; accO[nt][3] *= al1;
            }

            if (nh == 0) {
                if (kt < qt) cp_wait<1>(); else cp_wait<0>();
                __syncthreads();
            }

            // ---- O += P V (single-pass fp16; P post-softmax) ----
#pragma unroll
            for (int c2l = 0; c2l < 4; c2l++) {
                const int c2 = nh * 4 + c2l;
                uint32_t ph[4];
                ph[0] = pack_f16(sacc[2 * c2l][0],     sacc[2 * c2l][1]);
                ph[1] = pack_f16(sacc[2 * c2l][2],     sacc[2 * c2l][3]);
                ph[2] = pack_f16(sacc[2 * c2l + 1][0], sacc[2 * c2l + 1][1]);
                ph[3] = pack_f16(sacc[2 * c2l + 1][2], sacc[2 * c2l + 1][3]);

#pragma unroll
                for (int dq = 0; dq < 2; dq++) {
                    uint32_t vf4[2][4];
#pragma unroll
                    for (int j = 0; j < 2; j++) {
                        const int dp = dq * 2 + j;
                        const int vrow = c2 * 16 + v_kr;
                        ldsm4t(vf4[j], T2 + swz(vrow, dp * 2 + v_u));
                    }
#pragma unroll
                    for (int j = 0; j < 2; j++) {
                        const int dp = dq * 2 + j;
                        mma16816h(accO[2 * dp],     ph, vf4[j][0], vf4[j][1]);
                        mma16816h(accO[2 * dp + 1], ph, vf4[j][2], vf4[j][3]);
                    }
                }
            }
        }
    }

    // ---- epilogue: single fp16 into [B, S, E] for the O-projection ----
    const float i0 = 1.f / l0, i1 = 1.f / l1;
    const size_t ob0 = ((size_t)b * SEQ + row0) * EMB + h * HD;
    const size_t ob1 = ((size_t)b * SEQ + row1) * EMB + h * HD;
#pragma unroll
    for (int nt = 0; nt < 8; nt++) {
        const int col = nt * 8 + tq * 2;
        *(uint32_t*)(g_af + ob0 + col) =
            pack_f16(accO[nt][0] * i0, accO[nt][1] * i0);
        *(uint32_t*)(g_af + ob1 + col) =
            pack_f16(accO[nt][2] * i1, accO[nt][3] * i1);
    }
}

// ---------------------------------------------------------------------------
extern "C" void kernel_launch(void* const* d_in, const int* in_sizes, int n_in,
                              void* d_out, int out_size)
{
    const float* x    = (const float*)d_in[0];
    const int*   mask = (const int*)d_in[1];
    const float* wq   = (const float*)d_in[2];
    const float* wk   = (const float*)d_in[3];
    const float* wv   = (const float*)d_in[4];
    const float* wo   = (const float*)d_in[5];
    float* out = (float*)d_out;

    const int total4 = (MTOT * EMB + 4 * EMB * EMB) / 4;
    split_all_kernel<<<total4 / 256, 256>>>(x, wq, wk, wv, wo);

    cudaFuncSetAttribute(qkv_mma_kernel,
                         cudaFuncAttributeMaxDynamicSharedMemorySize, GEMM_SMEM);
    qkv_mma_kernel<<<dim3(MTOT / 128, EMB / 128, 3), 256, GEMM_SMEM>>>();

    cudaFuncSetAttribute(attn_hmma_kernel,
                         cudaFuncAttributeMaxDynamicSharedMemorySize, ASMEM);
    attn_hmma_kernel<<<dim3(SEQ / 128, NH, NB), 256, ASMEM>>>(mask);

    cudaFuncSetAttribute(oproj_mma_kernel,
                         cudaFuncAttributeMaxDynamicSharedMemorySize, GEMM_SMEM);
    oproj_mma_kernel<<<dim3(MTOT / 128, EMB / 128, 1), 256, GEMM_SMEM>>>(out);
}

// round 17
// speedup vs baseline: 2.7705x; 1.0989x over previous
#include <cuda_runtime.h>
#include <cuda_bf16.h>
#include <cuda_fp16.h>
#include <cstdint>

#define EMB  1024
#define NH   16
#define HD   64
#define SEQ  2048
#define NB   4
#define MTOT (NB * SEQ)   // 8192
#define NQT  (SEQ / 128)  // 16 q-tiles

// ---------------- scratch (__device__ globals; no allocs allowed) ----------
__device__ __half g_xf[(size_t)MTOT * EMB];
__device__ __half g_af[(size_t)MTOT * EMB];
__device__ __half g_wf[4][(size_t)EMB * EMB];
__device__ __half g_qf[(size_t)NB * NH * SEQ * HD];
__device__ __half g_kf[(size_t)NB * NH * SEQ * HD];
__device__ __half g_vf[(size_t)NB * NH * SEQ * HD];

// ---------------- helpers ---------------------------------------------------
__device__ __forceinline__ uint32_t smem_u32(const void* p) {
    uint32_t a;
    asm("{ .reg .u64 t; cvta.to.shared.u64 t, %1; cvt.u32.u64 %0, t; }"
        : "=r"(a) : "l"(p));
    return a;
}
__device__ __forceinline__ void ldsm4(uint32_t* r, uint32_t addr) {
    asm volatile("ldmatrix.sync.aligned.m8n8.x4.shared.b16 {%0,%1,%2,%3}, [%4];"
                 : "=r"(r[0]), "=r"(r[1]), "=r"(r[2]), "=r"(r[3]) : "r"(addr));
}
__device__ __forceinline__ void ldsm4t(uint32_t* r, uint32_t addr) {
    asm volatile("ldmatrix.sync.aligned.m8n8.x4.trans.shared.b16 {%0,%1,%2,%3}, [%4];"
                 : "=r"(r[0]), "=r"(r[1]), "=r"(r[2]), "=r"(r[3]) : "r"(addr));
}
__device__ __forceinline__ void mma16816h(float* c, const uint32_t* a,
                                          uint32_t b0, uint32_t b1) {
    asm volatile(
        "mma.sync.aligned.m16n8k16.row.col.f32.f16.f16.f32 "
        "{%0,%1,%2,%3}, {%4,%5,%6,%7}, {%8,%9}, {%0,%1,%2,%3};"
        : "+f"(c[0]), "+f"(c[1]), "+f"(c[2]), "+f"(c[3])
        : "r"(a[0]), "r"(a[1]), "r"(a[2]), "r"(a[3]), "r"(b0), "r"(b1));
}
__device__ __forceinline__ uint32_t pack_f16(float lo, float hi) {
    uint32_t r;
    asm("cvt.rn.f16x2.f32 %0, %1, %2;" : "=r"(r) : "f"(hi), "f"(lo));
    return r;
}
__device__ __forceinline__ float f16_round(float x) {
    return __half2float(__float2half_rn(x));
}
__device__ __forceinline__ void cp16cg(uint32_t saddr, const void* g) {
    asm volatile("cp.async.cg.shared.global [%0], [%1], 16;"
                 :: "r"(saddr), "l"(g) : "memory");
}
__device__ __forceinline__ void cp16ca(uint32_t saddr, const void* g) {
    asm volatile("cp.async.ca.shared.global [%0], [%1], 16;"
                 :: "r"(saddr), "l"(g) : "memory");
}
__device__ __forceinline__ void cp_commit() {
    asm volatile("cp.async.commit_group;" ::: "memory");
}
template <int N>
__device__ __forceinline__ void cp_wait() {
    asm volatile("cp.async.wait_group %0;" :: "n"(N) : "memory");
}

// ---------------- fused split prepass: x, w -> single fp16 -------------------
__global__ void __launch_bounds__(256)
split_all_kernel(const float* __restrict__ x,
                 const float* __restrict__ wq, const float* __restrict__ wk,
                 const float* __restrict__ wv, const float* __restrict__ wo)
{
    const long long i4 = ((long long)blockIdx.x * 256 + threadIdx.x) * 4;
    const float* src;
    __half* dst;
    long long off;
    if (i4 < (long long)MTOT * EMB) {
        src = x; dst = g_xf; off = i4;
    } else {
        const long long r = i4 - (long long)MTOT * EMB;
        const int w = (int)(r >> 20);                  // EMB*EMB == 2^20
        off = r & ((1ll << 20) - 1);
        src = (w == 0) ? wq : (w == 1) ? wk : (w == 2) ? wv : wo;
        dst = g_wf[w];
    }
    float4 v = *(const float4*)(src + off);
    *(uint32_t*)(dst + off)     = pack_f16(v.x, v.y);
    *(uint32_t*)(dst + off + 2) = pack_f16(v.z, v.w);
}

// ---------------- fp16 single-MMA GEMM, cp.async.ca pipeline, 2 CTA/SM -------
// C[m,n] = sum_k A[m,k]*B[n,k]; both single fp16, fp32 accumulate.
// MODE 0: fp32 row-major.  MODE 2: fp16 scatter to [B,H,S,D].
#define TS 40
#define TILE_B (128 * TS * 2)          // 10240 B per tile
#define STAGE_B (2 * TILE_B)           // 20480 B per stage (Af, Bf)
#define GEMM_SMEM (2 * STAGE_B)        // 40960 B

template <int MODE>
__device__ void hmma_gemm(const __half* __restrict__ Af_,
                          const __half* __restrict__ Bf_,
                          float* __restrict__ Cf,
                          __half* __restrict__ Ch,
                          float oscale)
{
    extern __shared__ char gsm[];
    const uint32_t sb = smem_u32(gsm);

    const int tid   = threadIdx.x;
    const int lane  = tid & 31;
    const int wid   = tid >> 5;
    const int warpM = wid & 3;
    const int warpN = wid >> 2;
    const int m0 = blockIdx.x * 128;
    const int n0 = blockIdx.y * 128;

    const int pr0 = tid >> 1;
    const int pu0 = (tid & 1) << 1;
    const __half* pA0 = Af_ + (size_t)(m0 + pr0) * EMB + pu0 * 8;
    const __half* pB0 = Bf_ + (size_t)(n0 + pr0) * EMB + pu0 * 8;
    const uint32_t so = (uint32_t)(pr0 * TS + pu0 * 8) * 2;

    float acc[2][8][4];
#pragma unroll
    for (int mt = 0; mt < 2; mt++)
#pragma unroll
        for (int nt = 0; nt < 8; nt++)
#pragma unroll
            for (int e = 0; e < 4; e++) acc[mt][nt][e] = 0.f;

    const int a_r = lane & 15;
    const int a_c = (lane >> 4) << 3;
    const int b_r = ((lane >> 4) << 3) + (lane & 7);
    const int b_c = ((lane >> 3) & 1) << 3;

    {
        const uint32_t stb = sb;
        cp16ca(stb + so,               pA0);
        cp16ca(stb + so + 16,          pA0 + 8);
        cp16ca(stb + TILE_B + so,      pB0);
        cp16ca(stb + TILE_B + so + 16, pB0 + 8);
        cp_commit();
    }

    for (int ch = 0; ch < EMB / 32; ch++) {
        const int st = ch & 1;
        cp_wait<0>();
        __syncthreads();
        if (ch + 1 < EMB / 32) {
            const int k1 = (ch + 1) * 32;
            const uint32_t stb = sb + (st ^ 1) * STAGE_B;
            cp16ca(stb + so,               pA0 + k1);
            cp16ca(stb + so + 16,          pA0 + k1 + 8);
            cp16ca(stb + TILE_B + so,      pB0 + k1);
            cp16ca(stb + TILE_B + so + 16, pB0 + k1 + 8);
            cp_commit();
        }

        const uint32_t stb = sb + st * STAGE_B;
        const uint32_t bAf = stb;
        const uint32_t bBf = stb + TILE_B;

#pragma unroll
        for (int ks = 0; ks < 2; ks++) {
            const int kb = ks << 4;
            uint32_t af[2][4];
#pragma unroll
            for (int mt = 0; mt < 2; mt++) {
                const uint32_t off =
                    (uint32_t)((warpM * 32 + mt * 16 + a_r) * TS + kb + a_c) * 2;
                ldsm4(af[mt], bAf + off);
            }
#pragma unroll
            for (int ng = 0; ng < 4; ng++) {
                const uint32_t off =
                    (uint32_t)((warpN * 64 + ng * 16 + b_r) * TS + kb + b_c) * 2;
                uint32_t bf[4];
                ldsm4(bf, bBf + off);
#pragma unroll
                for (int mt = 0; mt < 2; mt++) {
                    mma16816h(acc[mt][2 * ng],     af[mt], bf[0], bf[1]);
                    mma16816h(acc[mt][2 * ng + 1], af[mt], bf[2], bf[3]);
                }
            }
        }
    }

#pragma unroll
    for (int mt = 0; mt < 2; mt++) {
#pragma unroll
        for (int nt = 0; nt < 8; nt++) {
            const int row = m0 + warpM * 32 + mt * 16 + (lane >> 2);
            const int col = n0 + warpN * 64 + nt * 8 + ((lane & 3) << 1);
#pragma unroll
            for (int half = 0; half < 2; half++) {
                const int r = row + half * 8;
                float vx = acc[mt][nt][2 * half]     * oscale;
                float vy = acc[mt][nt][2 * half + 1] * oscale;
                if (MODE == 0) {
                    *(float2*)&Cf[(size_t)r * EMB + col] = make_float2(vx, vy);
                } else {
                    const int b = r >> 11, s = r & (SEQ - 1);
                    const int h = col >> 6, d = col & (HD - 1);
                    const size_t o = ((((size_t)b * NH + h) * SEQ + s) << 6) + d;
                    *(uint32_t*)(Ch + o) = pack_f16(vx, vy);
                }
            }
        }
    }
}

__global__ void __launch_bounds__(256, 2) qkv_mma_kernel()
{
    const int z = blockIdx.z;
    if (z == 0)
        hmma_gemm<2>(g_xf, g_wf[0], nullptr, g_qf, 0.125f);
    else if (z == 1)
        hmma_gemm<2>(g_xf, g_wf[1], nullptr, g_kf, 1.0f);
    else
        hmma_gemm<2>(g_xf, g_wf[2], nullptr, g_vf, 1.0f);
}
__global__ void __launch_bounds__(256, 2) oproj_mma_kernel(float* __restrict__ out)
{
    hmma_gemm<0>(g_af, g_wf[3], out, nullptr, 1.0f);
}

// ---------------- fp16 single-MMA flash attention ----------------------------
// QK: Q*K single pass (Q pre-scaled fp16 in regs, K single fp16).
// PV: P*V single pass.
// Tiles: T0 = K stage0, T2 = V (Q preload), T4 = K stage1.
// Heavy-first CTA order: qt = NQT-1 - blockIdx.x (causal tail balancing).
#define ATB 16384
#define ASMEM (3 * ATB + SEQ * 4)    // 57344 B

__device__ __forceinline__ uint32_t swz(int r, int u) {
    return (uint32_t)(r * 128 + (((u ^ r) & 7) << 4) + (u & ~7) * 16);
}

__global__ void __launch_bounds__(256, 2)
attn_hmma_kernel(const int* __restrict__ mask)
{
    extern __shared__ char sm[];
    const uint32_t T0 = smem_u32(sm);
    const uint32_t T2 = T0 + ATB;
    const uint32_t T4 = T0 + 2 * ATB;
    int* sMask = (int*)(sm + 3 * ATB);

    const int tid  = threadIdx.x;
    const int lane = tid & 31;
    const int wid  = tid >> 5;
    const int qt   = NQT - 1 - blockIdx.x;   // heaviest tiles scheduled first
    const int h    = blockIdx.y;
    const int b    = blockIdx.z;

    const size_t hb = ((size_t)b * NH + h) * SEQ * HD;
    const int* mrow = mask + b * SEQ;

    // preload: Q -> T2 (temp), K(0) -> T0, mask row
    for (int u = tid; u < 1024; u += 256) {
        const int r = u >> 3, c = u & 7;
        const uint32_t sw = swz(r, c);
        cp16cg(T2 + sw, g_qf + hb + (size_t)(qt * 128 + r) * HD + c * 8);
        cp16cg(T0 + sw, g_kf + hb + (size_t)r * HD + c * 8);
    }
    for (int i = tid; i < SEQ; i += 256) sMask[i] = mrow[i];
    cp_commit();
    cp_wait<0>();
    __syncthreads();

    const int a_r = lane & 15;
    const int a_u = lane >> 4;
    const int b_r = ((lane >> 4) << 3) + (lane & 7);
    const int b_u = (lane >> 3) & 1;
    const int v_kr = ((lane >> 3) & 1) * 8 + (lane & 7);
    const int v_u  = lane >> 4;

    const int tq   = lane & 3;
    const int row0 = qt * 128 + wid * 16 + (lane >> 2);
    const int row1 = row0 + 8;
    const int qrow = wid * 16 + a_r;

    // hoist Q fragments into registers
    uint32_t qf[4][4];
#pragma unroll
    for (int kc = 0; kc < 4; kc++)
        ldsm4(qf[kc], T2 + swz(qrow, kc * 2 + a_u));
    __syncthreads();    // T2 -> V tile

    float m0 = -1e30f, m1 = -1e30f, l0 = 0.f, l1 = 0.f;
    float accO[8][4];
#pragma unroll
    for (int nt = 0; nt < 8; nt++)
#pragma unroll
        for (int e = 0; e < 4; e++) accO[nt][e] = 0.f;

    for (int kt = 0; kt <= qt; kt++) {
        if (kt > 0) {
            cp_wait<0>();        // K(kt) landed
            __syncthreads();     // PV(kt-1) done -> V overwrite safe
        }

        // issue V(kt) (overlaps QK+softmax)
        for (int u = tid; u < 1024; u += 256) {
            const int r = u >> 3, c = u & 7;
            cp16cg(T2 + swz(r, c), g_vf + hb + (size_t)(kt * 128 + r) * HD + c * 8);
        }
        cp_commit();
        // issue K(kt+1) into the other stage (overlaps QK+PV)
        if (kt < qt) {
            const uint32_t Kn = ((kt + 1) & 1) ? T4 : T0;
            for (int u = tid; u < 1024; u += 256) {
                const int r = u >> 3, c = u & 7;
                cp16cg(Kn + swz(r, c),
                       g_kf + hb + (size_t)((kt + 1) * 128 + r) * HD + c * 8);
            }
            cp_commit();
        }

        const uint32_t bKf = (kt & 1) ? T4 : T0;

#pragma unroll
        for (int nh = 0; nh < 2; nh++) {
            float sacc[8][4];
#pragma unroll
            for (int nt = 0; nt < 8; nt++)
#pragma unroll
                for (int e = 0; e < 4; e++) sacc[nt][e] = 0.f;

#pragma unroll
            for (int kc = 0; kc < 4; kc++) {
#pragma unroll
                for (int np = 0; np < 2; np++) {
                    uint32_t kf4[2][4];
#pragma unroll
                    for (int j = 0; j < 2; j++) {
                        const int krow = (nh * 4 + np * 2 + j) * 16 + b_r;
                        ldsm4(kf4[j], bKf + swz(krow, kc * 2 + b_u));
                    }
#pragma unroll
                    for (int j = 0; j < 2; j++) {
                        const int n2 = np * 2 + j;
                        mma16816h(sacc[2 * n2],     qf[kc], kf4[j][0], kf4[j][1]);
                        mma16816h(sacc[2 * n2 + 1], qf[kc], kf4[j][2], kf4[j][3]);
                    }
                }
            }

#pragma unroll
            for (int nt = 0; nt < 8; nt++) {
                const int c0 = nh * 64 + nt * 8 + tq * 2;
                const int k0 = kt * 128 + c0;
                const bool v0 = sMask[k0] != 0;
                const bool v1 = sMask[k0 + 1] != 0;
                if (!(v0 && k0     <= row0)) sacc[nt][0] = -1e30f;
                if (!(v1 && k0 + 1 <= row0)) sacc[nt][1] = -1e30f;
                if (!(v0 && k0     <= row1)) sacc[nt][2] = -1e30f;
                if (!(v1 && k0 + 1 <= row1)) sacc[nt][3] = -1e30f;
            }

            float r0 = -1e30f, r1 = -1e30f;
#pragma unroll
            for (int nt = 0; nt < 8; nt++) {
                r0 = fmaxf(r0, fmaxf(sacc[nt][0], sacc[nt][1]));
                r1 = fmaxf(r1, fmaxf(sacc[nt][2], sacc[nt][3]));
            }
            r0 = fmaxf(r0, __shfl_xor_sync(0xffffffffu, r0, 1));
            r0 = fmaxf(r0, __shfl_xor_sync(0xffffffffu, r0, 2));
            r1 = fmaxf(r1, __shfl_xor_sync(0xffffffffu, r1, 1));
            r1 = fmaxf(r1, __shfl_xor_sync(0xffffffffu, r1, 2));

            const float mn0 = fmaxf(m0, r0), mn1 = fmaxf(m1, r1);
            const float al0 = __expf(m0 - mn0), al1 = __expf(m1 - mn1);
            m0 = mn0; m1 = mn1;

            float s0 = 0.f, s1 = 0.f;
#pragma unroll
            for (int nt = 0; nt < 8; nt++) {
                sacc[nt][0] = __expf(sacc[nt][0] - mn0); s0 += sacc[nt][0];
                sacc[nt][1] = __expf(sacc[nt][1] - mn0); s0 += sacc[nt][1];
                sacc[nt][2] = __expf(sacc[nt][2] - mn1); s1 += sacc[nt][2];
                sacc[nt][3] = __expf(sacc[nt][3] - mn1); s1 += sacc[nt][3];
            }
            s0 += __shfl_xor_sync(0xffffffffu, s0, 1);
            s0 += __shfl_xor_sync(0xffffffffu, s0, 2);
            s1 += __shfl_xor_sync(0xffffffffu, s1, 1);
            s1 += __shfl_xor_sync(0xffffffffu, s1, 2);
            l0 = l0 * al0 + s0;
            l1 = l1 * al1 + s1;
#pragma unroll
            for (int nt = 0; nt < 8; nt++) {
                accO[nt][0] *= al0; accO[nt][1] *= al0;
                accO[nt][2] *= al1; accO[nt][3] *= al1;
            }

            if (nh == 0) {
                // V must be resident before the first PV half
                if (kt < qt) cp_wait<1>(); else cp_wait<0>();
                __syncthreads();
            }

            // ---- O += P V (single-pass fp16) ----
#pragma unroll
            for (int c2l = 0; c2l < 4; c2l++) {
                const int c2 = nh * 4 + c2l;
                uint32_t ph[4];
                ph[0] = pack_f16(sacc[2 * c2l][0],     sacc[2 * c2l][1]);
                ph[1] = pack_f16(sacc[2 * c2l][2],     sacc[2 * c2l][3]);
                ph[2] = pack_f16(sacc[2 * c2l + 1][0], sacc[2 * c2l + 1][1]);
                ph[3] = pack_f16(sacc[2 * c2l + 1][2], sacc[2 * c2l + 1][3]);

#pragma unroll
                for (int dq = 0; dq < 2; dq++) {
                    uint32_t vf4[2][4];
#pragma unroll
                    for (int j = 0; j < 2; j++) {
                        const int dp = dq * 2 + j;
                        const int vrow = c2 * 16 + v_kr;
                        ldsm4t(vf4[j], T2 + swz(vrow, dp * 2 + v_u));
                    }
#pragma unroll
                    for (int j = 0; j < 2; j++) {
                        const int dp = dq * 2 + j;
                        mma16816h(accO[2 * dp],     ph, vf4[j][0], vf4[j][1]);
                        mma16816h(accO[2 * dp + 1], ph, vf4[j][2], vf4[j][3]);
                    }
                }
            }
        }
    }

    // ---- epilogue: single fp16 into [B, S, E] for the O-projection ----
    const float i0 = 1.f / l0, i1 = 1.f / l1;
    const size_t ob0 = ((size_t)b * SEQ + row0) * EMB + h * HD;
    const size_t ob1 = ((size_t)b * SEQ + row1) * EMB + h * HD;
#pragma unroll
    for (int nt = 0; nt < 8; nt++) {
        const int col = nt * 8 + tq * 2;
        *(uint32_t*)(g_af + ob0 + col) =
            pack_f16(accO[nt][0] * i0, accO[nt][1] * i0);
        *(uint32_t*)(g_af + ob1 + col) =
            pack_f16(accO[nt][2] * i1, accO[nt][3] * i1);
    }
}

// ---------------------------------------------------------------------------
extern "C" void kernel_launch(void* const* d_in, const int* in_sizes, int n_in,
                              void* d_out, int out_size)
{
    const float* x    = (const float*)d_in[0];
    const int*   mask = (const int*)d_in[1];
    const float* wq   = (const float*)d_in[2];
    const float* wk   = (const float*)d_in[3];
    const float* wv   = (const float*)d_in[4];
    const float* wo   = (const float*)d_in[5];
    float* out = (float*)d_out;

    const int total4 = (MTOT * EMB + 4 * EMB * EMB) / 4;
    split_all_kernel<<<total4 / 256, 256>>>(x, wq, wk, wv, wo);

    cudaFuncSetAttribute(qkv_mma_kernel,
                         cudaFuncAttributeMaxDynamicSharedMemorySize, GEMM_SMEM);
    qkv_mma_kernel<<<dim3(MTOT / 128, EMB / 128, 3), 256, GEMM_SMEM>>>();

    cudaFuncSetAttribute(attn_hmma_kernel,
                         cudaFuncAttributeMaxDynamicSharedMemorySize, ASMEM);
    attn_hmma_kernel<<<dim3(NQT, NH, NB), 256, ASMEM>>>(mask);

    cudaFuncSetAttribute(oproj_mma_kernel,
                         cudaFuncAttributeMaxDynamicSharedMemorySize, GEMM_SMEM);
    oproj_mma_kernel<<<dim3(MTOT / 128, EMB / 128, 1), 256, GEMM_SMEM>>>(out);
}